// round 1
// baseline (speedup 1.0000x reference)
#include <cuda_runtime.h>
#include <math.h>

#define BB  2
#define SS  2048
#define HIDN 2048
#define NH  16
#define NG  4
#define HD  128

// ---------------- scratch (static device globals; no allocs) ----------------
__device__ float g_q[(size_t)BB*SS*NH*HD];     // 4096 x 2048
__device__ float g_k[(size_t)BB*SS*NG*HD];     // 4096 x 512
__device__ float g_v[(size_t)BB*SS*NG*HD];     // 4096 x 512
__device__ float g_attn[(size_t)BB*SS*NH*HD];  // 4096 x 2048

// ---------------- generic tiled fp32 GEMM: C[M,N] = A[M,K] @ B[K,N] ---------
// BM=BN=128, BK=16, 256 threads, 8x8 per-thread microtile. All dims divisible.
__global__ void __launch_bounds__(256) gemm_kernel(const float* __restrict__ A,
                                                   const float* __restrict__ B,
                                                   float* __restrict__ C,
                                                   int M, int N, int K)
{
    __shared__ float As[128][16];
    __shared__ float Bs[16][128];
    int tid = threadIdx.x;
    int ty = tid >> 4;          // 0..15
    int tx = tid & 15;          // 0..15
    int bm0 = blockIdx.y * 128;
    int bn0 = blockIdx.x * 128;

    float acc[8][8];
#pragma unroll
    for (int i = 0; i < 8; i++)
#pragma unroll
        for (int j = 0; j < 8; j++) acc[i][j] = 0.f;

    for (int k0 = 0; k0 < K; k0 += 16) {
#pragma unroll
        for (int i = 0; i < 2; i++) {
            int f = tid + i * 256;           // 0..511
            int row = f >> 2;                // 0..127
            int c4  = (f & 3) * 4;           // 0,4,8,12
            *(float4*)&As[row][c4] =
                *(const float4*)&A[(size_t)(bm0 + row) * K + k0 + c4];
        }
#pragma unroll
        for (int i = 0; i < 2; i++) {
            int f = tid + i * 256;
            int row = f >> 5;                // 0..15
            int c4  = (f & 31) * 4;          // 0..124
            *(float4*)&Bs[row][c4] =
                *(const float4*)&B[(size_t)(k0 + row) * N + bn0 + c4];
        }
        __syncthreads();

#pragma unroll
        for (int k = 0; k < 16; k++) {
            float a[8], b[8];
#pragma unroll
            for (int i = 0; i < 8; i++) a[i] = As[ty * 8 + i][k];
            *(float4*)&b[0] = *(float4*)&Bs[k][tx * 8];
            *(float4*)&b[4] = *(float4*)&Bs[k][tx * 8 + 4];
#pragma unroll
            for (int i = 0; i < 8; i++)
#pragma unroll
                for (int j = 0; j < 8; j++)
                    acc[i][j] = fmaf(a[i], b[j], acc[i][j]);
        }
        __syncthreads();
    }

#pragma unroll
    for (int i = 0; i < 8; i++) {
        float* cp = &C[(size_t)(bm0 + ty * 8 + i) * N + bn0 + tx * 8];
        *(float4*)&cp[0] = *(float4*)&acc[i][0];
        *(float4*)&cp[4] = *(float4*)&acc[i][4];
    }
}

// ---------------- RoPE (in place on g_q, g_k) -------------------------------
// thread handles one (pos, head, pair) -> rotates (d, d+64)
__global__ void __launch_bounds__(256) rope_kernel(const float* __restrict__ cosb,
                                                   const float* __restrict__ sinb)
{
    int idx = blockIdx.x * blockDim.x + threadIdx.x;
    int p    = idx & 63;
    int rest = idx >> 6;
    int head = rest % (NH + NG);
    int bs   = rest / (NH + NG);        // 0..B*S-1
    int s    = bs & (SS - 1);

    float c  = cosb[s * HD + p];
    float sn = sinb[s * HD + p];

    float* buf;
    size_t base;
    if (head < NH) { buf = g_q; base = (size_t)bs * (NH * HD) + head * HD; }
    else           { buf = g_k; base = (size_t)bs * (NG * HD) + (head - NH) * HD; }

    float x0 = buf[base + p];
    float x1 = buf[base + p + 64];
    buf[base + p]      = x0 * c - x1 * sn;
    buf[base + p + 64] = x1 * c + x0 * sn;
}

// ---------------- flash attention -------------------------------------------
// grid (S/64, H, B), 256 threads. Tiles 64q x 64k, D=128, causal, online softmax.
// Thread owns O rows rg*4+i (rg=tid>>4), cols cg*8+j (cg=tid&15).
#define QP 132   // padded row length for Q/K/V tiles (floats)
#define SP 68    // padded row length for score tile
#define ATTN_SMEM ((3 * 64 * QP + 64 * SP) * 4)

__global__ void __launch_bounds__(256) attn_kernel()
{
    extern __shared__ float sm[];
    float* Qs = sm;                  // 64 x 132
    float* Ks = Qs + 64 * QP;        // 64 x 132
    float* Vs = Ks + 64 * QP;        // 64 x 132
    float* Ss = Vs + 64 * QP;        // 64 x 68

    const int tid = threadIdx.x;
    const int qt  = blockIdx.x;
    const int h   = blockIdx.y;
    const int b   = blockIdx.z;
    const int g   = h >> 2;          // rep = H/G = 4
    const float scale = 0.08838834764831845f;   // 1/sqrt(128)
    const int qrow0 = b * SS + qt * 64;
    const int rg = tid >> 4;         // 0..15
    const int cg = tid & 15;         // 0..15

    // load Q tile
#pragma unroll
    for (int i = 0; i < 8; i++) {
        int l = i * 1024 + tid * 4;
        int r = l >> 7, c = l & 127;
        *(float4*)&Qs[r * QP + c] =
            *(const float4*)&g_q[(size_t)(qrow0 + r) * (NH * HD) + h * HD + c];
    }

    float o[4][8];
    float mrow[4], lrow[4];
#pragma unroll
    for (int i = 0; i < 4; i++) {
        mrow[i] = -INFINITY; lrow[i] = 0.f;
#pragma unroll
        for (int j = 0; j < 8; j++) o[i][j] = 0.f;
    }

    for (int kt = 0; kt <= qt; kt++) {
        __syncthreads();   // prev-iter consumers done before overwriting K/V/S
        int krow0 = b * SS + kt * 64;
#pragma unroll
        for (int i = 0; i < 8; i++) {
            int l = i * 1024 + tid * 4;
            int r = l >> 7, c = l & 127;
            size_t goff = (size_t)(krow0 + r) * (NG * HD) + g * HD + c;
            *(float4*)&Ks[r * QP + c] = *(const float4*)&g_k[goff];
            *(float4*)&Vs[r * QP + c] = *(const float4*)&g_v[goff];
        }
        __syncthreads();

        // ---- scores: rows rg*4+i, cols cg+16*j, float4 dot over D ----
        float sacc[4][4];
#pragma unroll
        for (int i = 0; i < 4; i++)
#pragma unroll
            for (int j = 0; j < 4; j++) sacc[i][j] = 0.f;

        for (int k4 = 0; k4 < 128; k4 += 4) {
            float4 qv[4], kv[4];
#pragma unroll
            for (int i = 0; i < 4; i++)
                qv[i] = *(const float4*)&Qs[(rg * 4 + i) * QP + k4];
#pragma unroll
            for (int j = 0; j < 4; j++)
                kv[j] = *(const float4*)&Ks[(cg + 16 * j) * QP + k4];
#pragma unroll
            for (int i = 0; i < 4; i++)
#pragma unroll
                for (int j = 0; j < 4; j++) {
                    sacc[i][j] = fmaf(qv[i].x, kv[j].x, sacc[i][j]);
                    sacc[i][j] = fmaf(qv[i].y, kv[j].y, sacc[i][j]);
                    sacc[i][j] = fmaf(qv[i].z, kv[j].z, sacc[i][j]);
                    sacc[i][j] = fmaf(qv[i].w, kv[j].w, sacc[i][j]);
                }
        }
        bool diag = (kt == qt);
#pragma unroll
        for (int i = 0; i < 4; i++)
#pragma unroll
            for (int j = 0; j < 4; j++) {
                int r = rg * 4 + i, c = cg + 16 * j;
                float v = sacc[i][j] * scale;
                if (diag && c > r) v = -1e30f;
                Ss[r * SP + c] = v;
            }
        __syncthreads();

        // ---- pass1: row max ----
        float mnew[4];
#pragma unroll
        for (int i = 0; i < 4; i++) {
            const float* row = &Ss[(rg * 4 + i) * SP];
            float mv = mrow[i];
#pragma unroll
            for (int c = 0; c < 64; c += 4) {
                float4 s4 = *(const float4*)&row[c];
                mv = fmaxf(mv, fmaxf(fmaxf(s4.x, s4.y), fmaxf(s4.z, s4.w)));
            }
            mnew[i] = mv;
        }
        __syncthreads();

        // ---- pass2: write P in place (own 4 cols per row) ----
#pragma unroll
        for (int i = 0; i < 4; i++) {
            float* row = &Ss[(rg * 4 + i) * SP];
#pragma unroll
            for (int jj = 0; jj < 4; jj++) {
                int c = cg * 4 + jj;
                row[c] = __expf(row[c] - mnew[i]);
            }
        }
        __syncthreads();

        // ---- pass3: row sums + rescale ----
#pragma unroll
        for (int i = 0; i < 4; i++) {
            float alpha = __expf(mrow[i] - mnew[i]);
            const float* row = &Ss[(rg * 4 + i) * SP];
            float ps = 0.f;
#pragma unroll
            for (int c = 0; c < 64; c += 4) {
                float4 s4 = *(const float4*)&row[c];
                ps += (s4.x + s4.y) + (s4.z + s4.w);
            }
            lrow[i] = lrow[i] * alpha + ps;
            mrow[i] = mnew[i];
#pragma unroll
            for (int j = 0; j < 8; j++) o[i][j] *= alpha;
        }

        // ---- PV: O[i][j] += P[r][c] * V[c][cg*8+j] ----
        for (int c = 0; c < 64; c++) {
            float pa[4];
#pragma unroll
            for (int i = 0; i < 4; i++) pa[i] = Ss[(rg * 4 + i) * SP + c];
            float4 v0 = *(const float4*)&Vs[c * QP + cg * 8];
            float4 v1 = *(const float4*)&Vs[c * QP + cg * 8 + 4];
#pragma unroll
            for (int i = 0; i < 4; i++) {
                o[i][0] = fmaf(pa[i], v0.x, o[i][0]);
                o[i][1] = fmaf(pa[i], v0.y, o[i][1]);
                o[i][2] = fmaf(pa[i], v0.z, o[i][2]);
                o[i][3] = fmaf(pa[i], v0.w, o[i][3]);
                o[i][4] = fmaf(pa[i], v1.x, o[i][4]);
                o[i][5] = fmaf(pa[i], v1.y, o[i][5]);
                o[i][6] = fmaf(pa[i], v1.z, o[i][6]);
                o[i][7] = fmaf(pa[i], v1.w, o[i][7]);
            }
        }
    }

    // epilogue: normalize and write to g_attn [B*S, H*D]
#pragma unroll
    for (int i = 0; i < 4; i++) {
        float inv = 1.f / lrow[i];
        float4 r0, r1;
        r0.x = o[i][0] * inv; r0.y = o[i][1] * inv;
        r0.z = o[i][2] * inv; r0.w = o[i][3] * inv;
        r1.x = o[i][4] * inv; r1.y = o[i][5] * inv;
        r1.z = o[i][6] * inv; r1.w = o[i][7] * inv;
        float* op = &g_attn[(size_t)(qrow0 + rg * 4 + i) * (NH * HD) + h * HD + cg * 8];
        *(float4*)&op[0] = r0;
        *(float4*)&op[4] = r1;
    }
}

// ---------------- launch ----------------------------------------------------
extern "C" void kernel_launch(void* const* d_in, const int* in_sizes, int n_in,
                              void* d_out, int out_size)
{
    const float* x    = (const float*)d_in[0];
    const float* cosb = (const float*)d_in[1];
    const float* sinb = (const float*)d_in[2];
    const float* Wq   = (const float*)d_in[3];
    const float* Wk   = (const float*)d_in[4];
    const float* Wv   = (const float*)d_in[5];
    const float* Wo   = (const float*)d_in[6];
    float* out = (float*)d_out;

    float *qp, *kp, *vp, *ap;
    cudaGetSymbolAddress((void**)&qp, g_q);
    cudaGetSymbolAddress((void**)&kp, g_k);
    cudaGetSymbolAddress((void**)&vp, g_v);
    cudaGetSymbolAddress((void**)&ap, g_attn);

    const int M = BB * SS;   // 4096

    // QKV projections
    gemm_kernel<<<dim3((NH * HD) / 128, M / 128), 256>>>(x, Wq, qp, M, NH * HD, HIDN);
    gemm_kernel<<<dim3((NG * HD) / 128, M / 128), 256>>>(x, Wk, kp, M, NG * HD, HIDN);
    gemm_kernel<<<dim3((NG * HD) / 128, M / 128), 256>>>(x, Wv, vp, M, NG * HD, HIDN);

    // RoPE on q and k
    int nrope = BB * SS * (NH + NG) * 64;
    rope_kernel<<<nrope / 256, 256>>>(cosb, sinb);

    // flash attention
    cudaFuncSetAttribute(attn_kernel, cudaFuncAttributeMaxDynamicSharedMemorySize,
                         ATTN_SMEM);
    attn_kernel<<<dim3(SS / 64, NH, BB), 256, ATTN_SMEM>>>();

    // output projection
    gemm_kernel<<<dim3(HIDN / 128, M / 128), 256>>>(ap, Wo, out, M, HIDN, NH * HD);
}

// round 4
// speedup vs baseline: 1.8545x; 1.8545x over previous
#include <cuda_runtime.h>
#include <math.h>
#include <stdint.h>

#define BB  2
#define SS  2048
#define HIDN 2048
#define NH  16
#define NG  4
#define HD  128

// ---------------- scratch (static device globals; no allocs) ----------------
__device__ float g_xt  [(size_t)BB*SS*HIDN];    // rna(x)
__device__ float g_wqt [(size_t)HIDN*NH*HD];    // Wq^T [N,K] rna
__device__ float g_wkt [(size_t)HIDN*NG*HD];
__device__ float g_wvt [(size_t)HIDN*NG*HD];
__device__ float g_wot [(size_t)NH*HD*HIDN];    // Wo^T
__device__ float g_q   [(size_t)BB*SS*NH*HD];
__device__ float g_k   [(size_t)BB*SS*NG*HD];
__device__ float g_v   [(size_t)BB*SS*NG*HD];
__device__ float g_attn[(size_t)BB*SS*NH*HD];   // rna'd in attn epilogue

// ======================= helpers ============================================
__device__ __forceinline__ uint32_t smem_u32(const void* p) {
    uint32_t a;
    asm("{ .reg .u64 t; cvta.to.shared.u64 t, %1; cvt.u32.u64 %0, t; }"
        : "=r"(a) : "l"(p));
    return a;
}
__device__ __forceinline__ float rna_tf32(float v) {
    uint32_t r;
    asm("cvt.rna.tf32.f32 %0, %1;" : "=r"(r) : "f"(v));
    return __uint_as_float(r);
}
__device__ __forceinline__ void cp_async16(uint32_t daddr, const void* gptr) {
    asm volatile("cp.async.cg.shared.global [%0], [%1], 16;"
                 :: "r"(daddr), "l"(gptr) : "memory");
}
#define CP_COMMIT() asm volatile("cp.async.commit_group;" ::: "memory")
#define CP_WAIT(n)  asm volatile("cp.async.wait_group %0;" :: "n"(n) : "memory")

__device__ __forceinline__ void mma_tf32(float& d0, float& d1, float& d2, float& d3,
                                         uint32_t a0, uint32_t a1, uint32_t a2, uint32_t a3,
                                         uint32_t b0, uint32_t b1) {
    asm volatile(
        "mma.sync.aligned.m16n8k8.row.col.f32.tf32.tf32.f32 "
        "{%0,%1,%2,%3}, {%4,%5,%6,%7}, {%8,%9}, {%0,%1,%2,%3};"
        : "+f"(d0), "+f"(d1), "+f"(d2), "+f"(d3)
        : "r"(a0), "r"(a1), "r"(a2), "r"(a3), "r"(b0), "r"(b1));
}

// ======================= tf32 mma.sync GEMM =================================
// C[M, N_total] = A[M, K] (row-major) @ B^T, B stored [N_total, K] K-major.
// CTA tile 128x128x16, 256 threads (8 warps, 2x4), warp tile 64x32.
#define SROW 20              // padded smem row stride (floats)

__global__ void __launch_bounds__(256) gemm_mma(const float* __restrict__ A,
                                                const float* __restrict__ B,
                                                float* __restrict__ C,
                                                int N_total, int K)
{
    __shared__ float As[2][128 * SROW];
    __shared__ float Bs[2][128 * SROW];

    const int tid  = threadIdx.x;
    const int lane = tid & 31;
    const int wid  = tid >> 5;
    const int warpM = wid >> 2;          // 0..1
    const int warpN = wid & 3;           // 0..3
    const int r0 = lane >> 2;            // 0..7
    const int c0 = lane & 3;             // 0..3

    const int bm0 = blockIdx.y * 128;
    const int bn0 = blockIdx.x * 128;

    float acc[4][4][4];
#pragma unroll
    for (int mt = 0; mt < 4; mt++)
#pragma unroll
        for (int nt = 0; nt < 4; nt++)
#pragma unroll
            for (int r = 0; r < 4; r++) acc[mt][nt][r] = 0.f;

    const int nkt = K / 16;

    // ---- tile loader: 512 chunks of 16B per matrix, 2 per thread each ----
    auto load_tiles = [&](int buf, int k0) {
#pragma unroll
        for (int i = 0; i < 2; i++) {
            int ch  = tid + i * 256;     // 0..511
            int row = ch >> 2;
            int off = (ch & 3) * 4;
            cp_async16(smem_u32(&As[buf][row * SROW + off]),
                       &A[(size_t)(bm0 + row) * K + k0 + off]);
            cp_async16(smem_u32(&Bs[buf][row * SROW + off]),
                       &B[(size_t)(bn0 + row) * K + k0 + off]);
        }
    };

    load_tiles(0, 0);
    CP_COMMIT();

    for (int t = 0; t < nkt; t++) {
        if (t + 1 < nkt) {
            load_tiles((t + 1) & 1, (t + 1) * 16);
            CP_COMMIT();
            CP_WAIT(1);
        } else {
            CP_WAIT(0);
        }
        __syncthreads();

        const float* Ab = As[t & 1];
        const float* Bb = Bs[t & 1];
#pragma unroll
        for (int k8 = 0; k8 < 2; k8++) {
            uint32_t af[4][4];
#pragma unroll
            for (int mt = 0; mt < 4; mt++) {
                int row = warpM * 64 + mt * 16;
                int kk  = k8 * 8 + c0;
                af[mt][0] = __float_as_uint(Ab[(row + r0)     * SROW + kk]);
                af[mt][1] = __float_as_uint(Ab[(row + r0 + 8) * SROW + kk]);
                af[mt][2] = __float_as_uint(Ab[(row + r0)     * SROW + kk + 4]);
                af[mt][3] = __float_as_uint(Ab[(row + r0 + 8) * SROW + kk + 4]);
            }
            uint32_t bf[4][2];
#pragma unroll
            for (int nt = 0; nt < 4; nt++) {
                int col = warpN * 32 + nt * 8;
                int kk  = k8 * 8 + c0;
                bf[nt][0] = __float_as_uint(Bb[(col + r0) * SROW + kk]);
                bf[nt][1] = __float_as_uint(Bb[(col + r0) * SROW + kk + 4]);
            }
#pragma unroll
            for (int mt = 0; mt < 4; mt++)
#pragma unroll
                for (int nt = 0; nt < 4; nt++)
                    mma_tf32(acc[mt][nt][0], acc[mt][nt][1],
                             acc[mt][nt][2], acc[mt][nt][3],
                             af[mt][0], af[mt][1], af[mt][2], af[mt][3],
                             bf[nt][0], bf[nt][1]);
        }
        __syncthreads();
    }

    // ---- epilogue ----
#pragma unroll
    for (int mt = 0; mt < 4; mt++) {
        int row = bm0 + warpM * 64 + mt * 16 + r0;
#pragma unroll
        for (int nt = 0; nt < 4; nt++) {
            int col = bn0 + warpN * 32 + nt * 8 + c0 * 2;
            float2 v0 = make_float2(acc[mt][nt][0], acc[mt][nt][1]);
            float2 v1 = make_float2(acc[mt][nt][2], acc[mt][nt][3]);
            *(float2*)&C[(size_t)row * N_total + col]       = v0;
            *(float2*)&C[(size_t)(row + 8) * N_total + col] = v1;
        }
    }
}

// ======================= prep kernels =======================================
__global__ void __launch_bounds__(256) round_tf32_kernel(const float4* __restrict__ in,
                                                         float4* __restrict__ out, int n4)
{
    int i = blockIdx.x * blockDim.x + threadIdx.x;
    if (i < n4) {
        float4 v = in[i];
        v.x = rna_tf32(v.x); v.y = rna_tf32(v.y);
        v.z = rna_tf32(v.z); v.w = rna_tf32(v.w);
        out[i] = v;
    }
}

// out[n, k] = rna(in[k, n]); in is [K, N] row-major
__global__ void __launch_bounds__(256) transpose_rna_kernel(const float* __restrict__ in,
                                                            float* __restrict__ out,
                                                            int K, int N)
{
    __shared__ float t[32][33];
    int n0 = blockIdx.x * 32, k0 = blockIdx.y * 32;
    int x = threadIdx.x, y = threadIdx.y;
#pragma unroll
    for (int j = 0; j < 32; j += 8)
        t[y + j][x] = in[(size_t)(k0 + y + j) * N + n0 + x];
    __syncthreads();
#pragma unroll
    for (int j = 0; j < 32; j += 8)
        out[(size_t)(n0 + y + j) * K + k0 + x] = rna_tf32(t[x][y + j]);
}

// ---------------- RoPE (in place on g_q, g_k) -------------------------------
__global__ void __launch_bounds__(256) rope_kernel(const float* __restrict__ cosb,
                                                   const float* __restrict__ sinb)
{
    int idx = blockIdx.x * blockDim.x + threadIdx.x;
    int p    = idx & 63;
    int rest = idx >> 6;
    int head = rest % (NH + NG);
    int bs   = rest / (NH + NG);
    int s    = bs & (SS - 1);

    float c  = cosb[s * HD + p];
    float sn = sinb[s * HD + p];

    float* buf;
    size_t base;
    if (head < NH) { buf = g_q; base = (size_t)bs * (NH * HD) + head * HD; }
    else           { buf = g_k; base = (size_t)bs * (NG * HD) + (head - NH) * HD; }

    float x0 = buf[base + p];
    float x1 = buf[base + p + 64];
    buf[base + p]      = x0 * c - x1 * sn;
    buf[base + p + 64] = x1 * c + x0 * sn;
}

// ---------------- flash attention (fp32 SIMT, rna epilogue) -----------------
#define QP 132
#define SP 68
#define ATTN_SMEM ((3 * 64 * QP + 64 * SP) * 4)

__global__ void __launch_bounds__(256) attn_kernel()
{
    extern __shared__ float sm[];
    float* Qs = sm;
    float* Ks = Qs + 64 * QP;
    float* Vs = Ks + 64 * QP;
    float* Ss = Vs + 64 * QP;

    const int tid = threadIdx.x;
    const int qt  = blockIdx.x;
    const int h   = blockIdx.y;
    const int b   = blockIdx.z;
    const int g   = h >> 2;
    const float scale = 0.08838834764831845f;
    const int qrow0 = b * SS + qt * 64;
    const int rg = tid >> 4;
    const int cg = tid & 15;

#pragma unroll
    for (int i = 0; i < 8; i++) {
        int l = i * 1024 + tid * 4;
        int r = l >> 7, c = l & 127;
        *(float4*)&Qs[r * QP + c] =
            *(const float4*)&g_q[(size_t)(qrow0 + r) * (NH * HD) + h * HD + c];
    }

    float o[4][8];
    float mrow[4], lrow[4];
#pragma unroll
    for (int i = 0; i < 4; i++) {
        mrow[i] = -INFINITY; lrow[i] = 0.f;
#pragma unroll
        for (int j = 0; j < 8; j++) o[i][j] = 0.f;
    }

    for (int kt = 0; kt <= qt; kt++) {
        __syncthreads();
        int krow0 = b * SS + kt * 64;
#pragma unroll
        for (int i = 0; i < 8; i++) {
            int l = i * 1024 + tid * 4;
            int r = l >> 7, c = l & 127;
            size_t goff = (size_t)(krow0 + r) * (NG * HD) + g * HD + c;
            *(float4*)&Ks[r * QP + c] = *(const float4*)&g_k[goff];
            *(float4*)&Vs[r * QP + c] = *(const float4*)&g_v[goff];
        }
        __syncthreads();

        float sacc[4][4];
#pragma unroll
        for (int i = 0; i < 4; i++)
#pragma unroll
            for (int j = 0; j < 4; j++) sacc[i][j] = 0.f;

        for (int k4 = 0; k4 < 128; k4 += 4) {
            float4 qv[4], kv[4];
#pragma unroll
            for (int i = 0; i < 4; i++)
                qv[i] = *(const float4*)&Qs[(rg * 4 + i) * QP + k4];
#pragma unroll
            for (int j = 0; j < 4; j++)
                kv[j] = *(const float4*)&Ks[(cg + 16 * j) * QP + k4];
#pragma unroll
            for (int i = 0; i < 4; i++)
#pragma unroll
                for (int j = 0; j < 4; j++) {
                    sacc[i][j] = fmaf(qv[i].x, kv[j].x, sacc[i][j]);
                    sacc[i][j] = fmaf(qv[i].y, kv[j].y, sacc[i][j]);
                    sacc[i][j] = fmaf(qv[i].z, kv[j].z, sacc[i][j]);
                    sacc[i][j] = fmaf(qv[i].w, kv[j].w, sacc[i][j]);
                }
        }
        bool diag = (kt == qt);
#pragma unroll
        for (int i = 0; i < 4; i++)
#pragma unroll
            for (int j = 0; j < 4; j++) {
                int r = rg * 4 + i, c = cg + 16 * j;
                float v = sacc[i][j] * scale;
                if (diag && c > r) v = -1e30f;
                Ss[r * SP + c] = v;
            }
        __syncthreads();

        float mnew[4];
#pragma unroll
        for (int i = 0; i < 4; i++) {
            const float* row = &Ss[(rg * 4 + i) * SP];
            float mv = mrow[i];
#pragma unroll
            for (int c = 0; c < 64; c += 4) {
                float4 s4 = *(const float4*)&row[c];
                mv = fmaxf(mv, fmaxf(fmaxf(s4.x, s4.y), fmaxf(s4.z, s4.w)));
            }
            mnew[i] = mv;
        }
        __syncthreads();

#pragma unroll
        for (int i = 0; i < 4; i++) {
            float* row = &Ss[(rg * 4 + i) * SP];
#pragma unroll
            for (int jj = 0; jj < 4; jj++) {
                int c = cg * 4 + jj;
                row[c] = __expf(row[c] - mnew[i]);
            }
        }
        __syncthreads();

#pragma unroll
        for (int i = 0; i < 4; i++) {
            float alpha = __expf(mrow[i] - mnew[i]);
            const float* row = &Ss[(rg * 4 + i) * SP];
            float ps = 0.f;
#pragma unroll
            for (int c = 0; c < 64; c += 4) {
                float4 s4 = *(const float4*)&row[c];
                ps += (s4.x + s4.y) + (s4.z + s4.w);
            }
            lrow[i] = lrow[i] * alpha + ps;
            mrow[i] = mnew[i];
#pragma unroll
            for (int j = 0; j < 8; j++) o[i][j] *= alpha;
        }

        for (int c = 0; c < 64; c++) {
            float pa[4];
#pragma unroll
            for (int i = 0; i < 4; i++) pa[i] = Ss[(rg * 4 + i) * SP + c];
            float4 v0 = *(const float4*)&Vs[c * QP + cg * 8];
            float4 v1 = *(const float4*)&Vs[c * QP + cg * 8 + 4];
#pragma unroll
            for (int i = 0; i < 4; i++) {
                o[i][0] = fmaf(pa[i], v0.x, o[i][0]);
                o[i][1] = fmaf(pa[i], v0.y, o[i][1]);
                o[i][2] = fmaf(pa[i], v0.z, o[i][2]);
                o[i][3] = fmaf(pa[i], v0.w, o[i][3]);
                o[i][4] = fmaf(pa[i], v1.x, o[i][4]);
                o[i][5] = fmaf(pa[i], v1.y, o[i][5]);
                o[i][6] = fmaf(pa[i], v1.z, o[i][6]);
                o[i][7] = fmaf(pa[i], v1.w, o[i][7]);
            }
        }
    }

    // epilogue: normalize, round to tf32 (consumed by tf32 Wo GEMM)
#pragma unroll
    for (int i = 0; i < 4; i++) {
        float inv = 1.f / lrow[i];
        float4 r0, r1;
        r0.x = rna_tf32(o[i][0] * inv); r0.y = rna_tf32(o[i][1] * inv);
        r0.z = rna_tf32(o[i][2] * inv); r0.w = rna_tf32(o[i][3] * inv);
        r1.x = rna_tf32(o[i][4] * inv); r1.y = rna_tf32(o[i][5] * inv);
        r1.z = rna_tf32(o[i][6] * inv); r1.w = rna_tf32(o[i][7] * inv);
        float* op = &g_attn[(size_t)(qrow0 + rg * 4 + i) * (NH * HD) + h * HD + cg * 8];
        *(float4*)&op[0] = r0;
        *(float4*)&op[4] = r1;
    }
}

// ======================= host side ==========================================
extern "C" void kernel_launch(void* const* d_in, const int* in_sizes, int n_in,
                              void* d_out, int out_size)
{
    const float* x    = (const float*)d_in[0];
    const float* cosb = (const float*)d_in[1];
    const float* sinb = (const float*)d_in[2];
    const float* Wq   = (const float*)d_in[3];
    const float* Wk   = (const float*)d_in[4];
    const float* Wv   = (const float*)d_in[5];
    const float* Wo   = (const float*)d_in[6];
    float* out = (float*)d_out;

    float *xt, *wqt, *wkt, *wvt, *wot, *qp, *kp, *vp, *ap;
    cudaGetSymbolAddress((void**)&xt,  g_xt);
    cudaGetSymbolAddress((void**)&wqt, g_wqt);
    cudaGetSymbolAddress((void**)&wkt, g_wkt);
    cudaGetSymbolAddress((void**)&wvt, g_wvt);
    cudaGetSymbolAddress((void**)&wot, g_wot);
    cudaGetSymbolAddress((void**)&qp,  g_q);
    cudaGetSymbolAddress((void**)&kp,  g_k);
    cudaGetSymbolAddress((void**)&vp,  g_v);
    cudaGetSymbolAddress((void**)&ap,  g_attn);

    const int M = BB * SS;       // 4096

    cudaFuncSetAttribute(attn_kernel, cudaFuncAttributeMaxDynamicSharedMemorySize, ATTN_SMEM);

    // 1) rna(x), weight transposes (+rna)
    int n4 = M * HIDN / 4;
    round_tf32_kernel<<<(n4 + 255) / 256, 256>>>((const float4*)x, (float4*)xt, n4);
    transpose_rna_kernel<<<dim3((NH * HD) / 32, HIDN / 32), dim3(32, 8)>>>(Wq, wqt, HIDN, NH * HD);
    transpose_rna_kernel<<<dim3((NG * HD) / 32, HIDN / 32), dim3(32, 8)>>>(Wk, wkt, HIDN, NG * HD);
    transpose_rna_kernel<<<dim3((NG * HD) / 32, HIDN / 32), dim3(32, 8)>>>(Wv, wvt, HIDN, NG * HD);
    transpose_rna_kernel<<<dim3(HIDN / 32, (NH * HD) / 32), dim3(32, 8)>>>(Wo, wot, NH * HD, HIDN);

    // 2) QKV projections (tf32 mma.sync)
    gemm_mma<<<dim3((NH * HD) / 128, M / 128), 256>>>(xt, wqt, qp, NH * HD, HIDN);
    gemm_mma<<<dim3((NG * HD) / 128, M / 128), 256>>>(xt, wkt, kp, NG * HD, HIDN);
    gemm_mma<<<dim3((NG * HD) / 128, M / 128), 256>>>(xt, wvt, vp, NG * HD, HIDN);

    // 3) RoPE
    int nrope = BB * SS * (NH + NG) * 64;
    rope_kernel<<<nrope / 256, 256>>>(cosb, sinb);

    // 4) attention (fp32 SIMT, rna epilogue)
    attn_kernel<<<dim3(SS / 64, NH, BB), 256, ATTN_SMEM>>>();

    // 5) output projection
    gemm_mma<<<dim3(HIDN / 128, M / 128), 256>>>(ap, wot, out, HIDN, NH * HD);
}

// round 6
// speedup vs baseline: 3.2323x; 1.7430x over previous
#include <cuda_runtime.h>
#include <math.h>
#include <stdint.h>

#define BB  2
#define SS  2048
#define HIDN 2048
#define NH  16
#define NG  4
#define HD  128

// ---------------- scratch (static device globals; no allocs) ----------------
__device__ float g_xt  [(size_t)BB*SS*HIDN];    // rna(x)
__device__ float g_wqt [(size_t)HIDN*NH*HD];    // Wq^T [N,K] rna
__device__ float g_wkt [(size_t)HIDN*NG*HD];
__device__ float g_wvt [(size_t)HIDN*NG*HD];
__device__ float g_wot [(size_t)NH*HD*HIDN];    // Wo^T
__device__ float g_q   [(size_t)BB*SS*NH*HD];   // rna'd by rope
__device__ float g_k   [(size_t)BB*SS*NG*HD];   // rna'd by rope
__device__ float g_v   [(size_t)BB*SS*NG*HD];
__device__ float g_attn[(size_t)BB*SS*NH*HD];   // rna'd in attn epilogue

// ======================= helpers ============================================
__device__ __forceinline__ uint32_t smem_u32(const void* p) {
    uint32_t a;
    asm("{ .reg .u64 t; cvta.to.shared.u64 t, %1; cvt.u32.u64 %0, t; }"
        : "=r"(a) : "l"(p));
    return a;
}
__device__ __forceinline__ float rna_tf32(float v) {
    uint32_t r;
    asm("cvt.rna.tf32.f32 %0, %1;" : "=r"(r) : "f"(v));
    return __uint_as_float(r);
}
__device__ __forceinline__ void cp_async16(uint32_t daddr, const void* gptr) {
    asm volatile("cp.async.cg.shared.global [%0], [%1], 16;"
                 :: "r"(daddr), "l"(gptr) : "memory");
}
#define CP_COMMIT() asm volatile("cp.async.commit_group;" ::: "memory")
#define CP_WAIT(n)  asm volatile("cp.async.wait_group %0;" :: "n"(n) : "memory")

__device__ __forceinline__ void mma_tf32(float& d0, float& d1, float& d2, float& d3,
                                         uint32_t a0, uint32_t a1, uint32_t a2, uint32_t a3,
                                         uint32_t b0, uint32_t b1) {
    asm volatile(
        "mma.sync.aligned.m16n8k8.row.col.f32.tf32.tf32.f32 "
        "{%0,%1,%2,%3}, {%4,%5,%6,%7}, {%8,%9}, {%0,%1,%2,%3};"
        : "+f"(d0), "+f"(d1), "+f"(d2), "+f"(d3)
        : "r"(a0), "r"(a1), "r"(a2), "r"(a3), "r"(b0), "r"(b1));
}

// ======================= tf32 mma.sync GEMM (unchanged, works) ==============
#define SROW 20

__global__ void __launch_bounds__(256) gemm_mma(const float* __restrict__ A,
                                                const float* __restrict__ B,
                                                float* __restrict__ C,
                                                int N_total, int K)
{
    __shared__ float As[2][128 * SROW];
    __shared__ float Bs[2][128 * SROW];

    const int tid  = threadIdx.x;
    const int lane = tid & 31;
    const int wid  = tid >> 5;
    const int warpM = wid >> 2;
    const int warpN = wid & 3;
    const int r0 = lane >> 2;
    const int c0 = lane & 3;

    const int bm0 = blockIdx.y * 128;
    const int bn0 = blockIdx.x * 128;

    float acc[4][4][4];
#pragma unroll
    for (int mt = 0; mt < 4; mt++)
#pragma unroll
        for (int nt = 0; nt < 4; nt++)
#pragma unroll
            for (int r = 0; r < 4; r++) acc[mt][nt][r] = 0.f;

    const int nkt = K / 16;

    auto load_tiles = [&](int buf, int k0) {
#pragma unroll
        for (int i = 0; i < 2; i++) {
            int ch  = tid + i * 256;
            int row = ch >> 2;
            int off = (ch & 3) * 4;
            cp_async16(smem_u32(&As[buf][row * SROW + off]),
                       &A[(size_t)(bm0 + row) * K + k0 + off]);
            cp_async16(smem_u32(&Bs[buf][row * SROW + off]),
                       &B[(size_t)(bn0 + row) * K + k0 + off]);
        }
    };

    load_tiles(0, 0);
    CP_COMMIT();

    for (int t = 0; t < nkt; t++) {
        if (t + 1 < nkt) {
            load_tiles((t + 1) & 1, (t + 1) * 16);
            CP_COMMIT();
            CP_WAIT(1);
        } else {
            CP_WAIT(0);
        }
        __syncthreads();

        const float* Ab = As[t & 1];
        const float* Bb = Bs[t & 1];
#pragma unroll
        for (int k8 = 0; k8 < 2; k8++) {
            uint32_t af[4][4];
#pragma unroll
            for (int mt = 0; mt < 4; mt++) {
                int row = warpM * 64 + mt * 16;
                int kk  = k8 * 8 + c0;
                af[mt][0] = __float_as_uint(Ab[(row + r0)     * SROW + kk]);
                af[mt][1] = __float_as_uint(Ab[(row + r0 + 8) * SROW + kk]);
                af[mt][2] = __float_as_uint(Ab[(row + r0)     * SROW + kk + 4]);
                af[mt][3] = __float_as_uint(Ab[(row + r0 + 8) * SROW + kk + 4]);
            }
            uint32_t bf[4][2];
#pragma unroll
            for (int nt = 0; nt < 4; nt++) {
                int col = warpN * 32 + nt * 8;
                int kk  = k8 * 8 + c0;
                bf[nt][0] = __float_as_uint(Bb[(col + r0) * SROW + kk]);
                bf[nt][1] = __float_as_uint(Bb[(col + r0) * SROW + kk + 4]);
            }
#pragma unroll
            for (int mt = 0; mt < 4; mt++)
#pragma unroll
                for (int nt = 0; nt < 4; nt++)
                    mma_tf32(acc[mt][nt][0], acc[mt][nt][1],
                             acc[mt][nt][2], acc[mt][nt][3],
                             af[mt][0], af[mt][1], af[mt][2], af[mt][3],
                             bf[nt][0], bf[nt][1]);
        }
        __syncthreads();
    }

#pragma unroll
    for (int mt = 0; mt < 4; mt++) {
        int row = bm0 + warpM * 64 + mt * 16 + r0;
#pragma unroll
        for (int nt = 0; nt < 4; nt++) {
            int col = bn0 + warpN * 32 + nt * 8 + c0 * 2;
            float2 v0 = make_float2(acc[mt][nt][0], acc[mt][nt][1]);
            float2 v1 = make_float2(acc[mt][nt][2], acc[mt][nt][3]);
            *(float2*)&C[(size_t)row * N_total + col]       = v0;
            *(float2*)&C[(size_t)(row + 8) * N_total + col] = v1;
        }
    }
}

// ======================= prep kernels =======================================
__global__ void __launch_bounds__(256) round_tf32_kernel(const float4* __restrict__ in,
                                                         float4* __restrict__ out, int n4)
{
    int i = blockIdx.x * blockDim.x + threadIdx.x;
    if (i < n4) {
        float4 v = in[i];
        v.x = rna_tf32(v.x); v.y = rna_tf32(v.y);
        v.z = rna_tf32(v.z); v.w = rna_tf32(v.w);
        out[i] = v;
    }
}

__global__ void __launch_bounds__(256) transpose_rna_kernel(const float* __restrict__ in,
                                                            float* __restrict__ out,
                                                            int K, int N)
{
    __shared__ float t[32][33];
    int n0 = blockIdx.x * 32, k0 = blockIdx.y * 32;
    int x = threadIdx.x, y = threadIdx.y;
#pragma unroll
    for (int j = 0; j < 32; j += 8)
        t[y + j][x] = in[(size_t)(k0 + y + j) * N + n0 + x];
    __syncthreads();
#pragma unroll
    for (int j = 0; j < 32; j += 8)
        out[(size_t)(n0 + y + j) * K + k0 + x] = rna_tf32(t[x][y + j]);
}

// ---------------- RoPE (in place, rna outputs for tf32 consumers) -----------
__global__ void __launch_bounds__(256) rope_kernel(const float* __restrict__ cosb,
                                                   const float* __restrict__ sinb)
{
    int idx = blockIdx.x * blockDim.x + threadIdx.x;
    int p    = idx & 63;
    int rest = idx >> 6;
    int head = rest % (NH + NG);
    int bs   = rest / (NH + NG);
    int s    = bs & (SS - 1);

    float c  = cosb[s * HD + p];
    float sn = sinb[s * HD + p];

    float* buf;
    size_t base;
    if (head < NH) { buf = g_q; base = (size_t)bs * (NH * HD) + head * HD; }
    else           { buf = g_k; base = (size_t)bs * (NG * HD) + (head - NH) * HD; }

    float x0 = buf[base + p];
    float x1 = buf[base + p + 64];
    buf[base + p]      = rna_tf32(x0 * c - x1 * sn);
    buf[base + p + 64] = rna_tf32(x1 * c + x0 * sn);
}

// ======================= flash attention (tf32 mma.sync) ====================
// CTA: 128 q rows x (64-col K tiles), 256 threads = 8 warps, warp = m16 slab.
// smem layout (floats):
#define AQP 132                        // Q/K/V row stride
#define ASP 68                         // S row stride
#define A_QS   0
#define A_KS   (A_QS + 128 * AQP)      // 16896
#define A_VS   (A_KS + 64 * AQP)       // 25344
#define A_SS   (A_VS + 64 * AQP)       // 33792
#define A_M    (A_SS + 128 * ASP)      // 42496
#define A_L    (A_M + 128)
#define A_ALPH (A_L + 128)
#define A_PMAX (A_ALPH + 128)          // [2][128]
#define A_PSUM (A_PMAX + 256)          // [2][128]
#define ATTN_SMEM ((A_PSUM + 256) * 4)

__global__ void __launch_bounds__(256) attn_mma_kernel()
{
    extern __shared__ float sm[];
    float* Qs = sm + A_QS;
    float* Ks = sm + A_KS;
    float* Vs = sm + A_VS;
    float* Ss = sm + A_SS;
    float* Ms = sm + A_M;
    float* Ls = sm + A_L;
    float* Al = sm + A_ALPH;
    float* Pm = sm + A_PMAX;
    float* Psum = sm + A_PSUM;

    const int tid  = threadIdx.x;
    const int lane = tid & 31;
    const int wid  = tid >> 5;          // 0..7
    const int r0   = lane >> 2;         // 0..7
    const int c0   = lane & 3;          // 0..3
    const int slab = wid * 16;

    const int qt = gridDim.x - 1 - blockIdx.x;   // big tiles first
    const int h  = blockIdx.y;
    const int b  = blockIdx.z;
    const int g  = h >> 2;
    const float scale = 0.08838834764831845f;
    const int qrow0 = qt * 128;                  // within sequence
    const int grow0 = b * SS + qrow0;            // global token row

    // ---- load Q tile (already rna'd) ----
#pragma unroll
    for (int i = 0; i < 16; i++) {
        int l = i * 1024 + tid * 4;
        int r = l >> 7, c = l & 127;
        *(float4*)&Qs[r * AQP + c] =
            *(const float4*)&g_q[(size_t)(grow0 + r) * (NH * HD) + h * HD + c];
    }

    // ---- init state ----
    if (tid < 128) { Ms[tid] = -INFINITY; Ls[tid] = 0.f; }

    float o[16][4];
#pragma unroll
    for (int nt = 0; nt < 16; nt++)
#pragma unroll
        for (int r = 0; r < 4; r++) o[nt][r] = 0.f;

    const int nkt = 2 * qt + 2;

    for (int kt = 0; kt < nkt; kt++) {
        __syncthreads();                 // prev iter consumers done
        const int krow0 = b * SS + kt * 64;
        // ---- load K and V tiles (V gets rna) ----
#pragma unroll
        for (int i = 0; i < 8; i++) {
            int l = i * 1024 + tid * 4;
            int r = l >> 7, c = l & 127;
            size_t goff = (size_t)(krow0 + r) * (NG * HD) + g * HD + c;
            *(float4*)&Ks[r * AQP + c] = *(const float4*)&g_k[goff];
            float4 v = *(const float4*)&g_v[goff];
            v.x = rna_tf32(v.x); v.y = rna_tf32(v.y);
            v.z = rna_tf32(v.z); v.w = rna_tf32(v.w);
            *(float4*)&Vs[r * AQP + c] = v;
        }
        __syncthreads();

        // ---- QK^T : warp slab (16 rows) x 64 cols, K=128 ----
        float sacc[8][4];
#pragma unroll
        for (int nt = 0; nt < 8; nt++)
#pragma unroll
            for (int r = 0; r < 4; r++) sacc[nt][r] = 0.f;

#pragma unroll
        for (int k8 = 0; k8 < 16; k8++) {
            int kk = k8 * 8 + c0;
            uint32_t a0 = __float_as_uint(Qs[(slab + r0)     * AQP + kk]);
            uint32_t a1 = __float_as_uint(Qs[(slab + r0 + 8) * AQP + kk]);
            uint32_t a2 = __float_as_uint(Qs[(slab + r0)     * AQP + kk + 4]);
            uint32_t a3 = __float_as_uint(Qs[(slab + r0 + 8) * AQP + kk + 4]);
#pragma unroll
            for (int nt = 0; nt < 8; nt++) {
                uint32_t b0 = __float_as_uint(Ks[(nt * 8 + r0) * AQP + kk]);
                uint32_t b1 = __float_as_uint(Ks[(nt * 8 + r0) * AQP + kk + 4]);
                mma_tf32(sacc[nt][0], sacc[nt][1], sacc[nt][2], sacc[nt][3],
                         a0, a1, a2, a3, b0, b1);
            }
        }

        // ---- scale + causal mask + store S ----
        const int rg_a = qrow0 + slab + r0;      // global q row (within seq)
        const int rg_b = rg_a + 8;
#pragma unroll
        for (int nt = 0; nt < 8; nt++) {
            int cg = kt * 64 + nt * 8 + 2 * c0;  // global k col
            float s0 = sacc[nt][0] * scale, s1 = sacc[nt][1] * scale;
            float s2 = sacc[nt][2] * scale, s3 = sacc[nt][3] * scale;
            if (cg     > rg_a) s0 = -1e30f;
            if (cg + 1 > rg_a) s1 = -1e30f;
            if (cg     > rg_b) s2 = -1e30f;
            if (cg + 1 > rg_b) s3 = -1e30f;
            *(float2*)&Ss[(slab + r0) * ASP + nt * 8 + 2 * c0]     = make_float2(s0, s1);
            *(float2*)&Ss[(slab + r0 + 8) * ASP + nt * 8 + 2 * c0] = make_float2(s2, s3);
        }
        __syncthreads();

        // ---- softmax phase A: partial row max (2 threads per row) ----
        {
            int row = tid & 127, half = tid >> 7;
            const float* srow = &Ss[row * ASP + half * 32];
            float mv = -INFINITY;
#pragma unroll
            for (int c = 0; c < 32; c += 4) {
                float4 s4 = *(const float4*)&srow[c];
                mv = fmaxf(mv, fmaxf(fmaxf(s4.x, s4.y), fmaxf(s4.z, s4.w)));
            }
            Pm[half * 128 + row] = mv;
        }
        __syncthreads();
        // ---- phase B: new max, alpha ----
        if (tid < 128) {
            float mold = Ms[tid];
            float mnew = fmaxf(mold, fmaxf(Pm[tid], Pm[128 + tid]));
            Ms[tid] = mnew;
            Al[tid] = __expf(mold - mnew);
        }
        __syncthreads();
        // ---- phase C: exp + partial sums, write P (rna) ----
        {
            int row = tid & 127, half = tid >> 7;
            float mnew = Ms[row];
            float* srow = &Ss[row * ASP + half * 32];
            float ps = 0.f;
#pragma unroll
            for (int c = 0; c < 32; c++) {
                float e = __expf(srow[c] - mnew);
                ps += e;
                srow[c] = rna_tf32(e);
            }
            Psum[half * 128 + row] = ps;
        }
        __syncthreads();
        // ---- phase D: update l ----
        if (tid < 128)
            Ls[tid] = Ls[tid] * Al[tid] + Psum[tid] + Psum[128 + tid];

        // ---- rescale O ----
        float aa = Al[slab + r0];
        float ab = Al[slab + r0 + 8];
#pragma unroll
        for (int nt = 0; nt < 16; nt++) {
            o[nt][0] *= aa; o[nt][1] *= aa;
            o[nt][2] *= ab; o[nt][3] *= ab;
        }

        // ---- P @ V : M=16 slab, N=128 (d), K=64 (kcols) ----
#pragma unroll
        for (int k8 = 0; k8 < 8; k8++) {
            int kk = k8 * 8 + c0;
            uint32_t a0 = __float_as_uint(Ss[(slab + r0)     * ASP + kk]);
            uint32_t a1 = __float_as_uint(Ss[(slab + r0 + 8) * ASP + kk]);
            uint32_t a2 = __float_as_uint(Ss[(slab + r0)     * ASP + kk + 4]);
            uint32_t a3 = __float_as_uint(Ss[(slab + r0 + 8) * ASP + kk + 4]);
#pragma unroll
            for (int nt = 0; nt < 16; nt++) {
                uint32_t b0 = __float_as_uint(Vs[kk * AQP + nt * 8 + r0]);
                uint32_t b1 = __float_as_uint(Vs[(kk + 4) * AQP + nt * 8 + r0]);
                mma_tf32(o[nt][0], o[nt][1], o[nt][2], o[nt][3],
                         a0, a1, a2, a3, b0, b1);
            }
        }
    }

    __syncthreads();
    // ---- epilogue: normalize, rna, store ----
    float la = 1.f / Ls[slab + r0];
    float lb = 1.f / Ls[slab + r0 + 8];
    const size_t rowa = (size_t)(grow0 + slab + r0) * (NH * HD) + h * HD;
    const size_t rowb = (size_t)(grow0 + slab + r0 + 8) * (NH * HD) + h * HD;
#pragma unroll
    for (int nt = 0; nt < 16; nt++) {
        int c = nt * 8 + 2 * c0;
        float2 v0 = make_float2(rna_tf32(o[nt][0] * la), rna_tf32(o[nt][1] * la));
        float2 v1 = make_float2(rna_tf32(o[nt][2] * lb), rna_tf32(o[nt][3] * lb));
        *(float2*)&g_attn[rowa + c] = v0;
        *(float2*)&g_attn[rowb + c] = v1;
    }
}

// ======================= host side ==========================================
extern "C" void kernel_launch(void* const* d_in, const int* in_sizes, int n_in,
                              void* d_out, int out_size)
{
    const float* x    = (const float*)d_in[0];
    const float* cosb = (const float*)d_in[1];
    const float* sinb = (const float*)d_in[2];
    const float* Wq   = (const float*)d_in[3];
    const float* Wk   = (const float*)d_in[4];
    const float* Wv   = (const float*)d_in[5];
    const float* Wo   = (const float*)d_in[6];
    float* out = (float*)d_out;

    float *xt, *wqt, *wkt, *wvt, *wot, *qp, *kp, *vp, *ap;
    cudaGetSymbolAddress((void**)&xt,  g_xt);
    cudaGetSymbolAddress((void**)&wqt, g_wqt);
    cudaGetSymbolAddress((void**)&wkt, g_wkt);
    cudaGetSymbolAddress((void**)&wvt, g_wvt);
    cudaGetSymbolAddress((void**)&wot, g_wot);
    cudaGetSymbolAddress((void**)&qp,  g_q);
    cudaGetSymbolAddress((void**)&kp,  g_k);
    cudaGetSymbolAddress((void**)&vp,  g_v);
    cudaGetSymbolAddress((void**)&ap,  g_attn);

    const int M = BB * SS;       // 4096

    cudaFuncSetAttribute(attn_mma_kernel, cudaFuncAttributeMaxDynamicSharedMemorySize,
                         ATTN_SMEM);

    // 1) rna(x), weight transposes (+rna)
    int n4 = M * HIDN / 4;
    round_tf32_kernel<<<(n4 + 255) / 256, 256>>>((const float4*)x, (float4*)xt, n4);
    transpose_rna_kernel<<<dim3((NH * HD) / 32, HIDN / 32), dim3(32, 8)>>>(Wq, wqt, HIDN, NH * HD);
    transpose_rna_kernel<<<dim3((NG * HD) / 32, HIDN / 32), dim3(32, 8)>>>(Wk, wkt, HIDN, NG * HD);
    transpose_rna_kernel<<<dim3((NG * HD) / 32, HIDN / 32), dim3(32, 8)>>>(Wv, wvt, HIDN, NG * HD);
    transpose_rna_kernel<<<dim3(HIDN / 32, (NH * HD) / 32), dim3(32, 8)>>>(Wo, wot, NH * HD, HIDN);

    // 2) QKV projections (tf32 mma.sync)
    gemm_mma<<<dim3((NH * HD) / 128, M / 128), 256>>>(xt, wqt, qp, NH * HD, HIDN);
    gemm_mma<<<dim3((NG * HD) / 128, M / 128), 256>>>(xt, wkt, kp, NG * HD, HIDN);
    gemm_mma<<<dim3((NG * HD) / 128, M / 128), 256>>>(xt, wvt, vp, NG * HD, HIDN);

    // 3) RoPE (+rna)
    int nrope = BB * SS * (NH + NG) * 64;
    rope_kernel<<<nrope / 256, 256>>>(cosb, sinb);

    // 4) attention (tf32 mma.sync flash)
    attn_mma_kernel<<<dim3(SS / 128, NH, BB), 256, ATTN_SMEM>>>();

    // 5) output projection
    gemm_mma<<<dim3(HIDN / 128, M / 128), 256>>>(ap, wot, out, HIDN, NH * HD);
}

// round 7
// speedup vs baseline: 3.4454x; 1.0659x over previous
#include <cuda_runtime.h>
#include <math.h>
#include <stdint.h>

#define BB  2
#define SS  2048
#define HIDN 2048
#define NH  16
#define NG  4
#define HD  128

// ---------------- scratch (static device globals; no allocs) ----------------
__device__ float g_xt  [(size_t)BB*SS*HIDN];    // rna(x)
__device__ float g_wqt [(size_t)HIDN*NH*HD];    // Wq^T [N,K] rna
__device__ float g_wkt [(size_t)HIDN*NG*HD];
__device__ float g_wvt [(size_t)HIDN*NG*HD];
__device__ float g_wot [(size_t)NH*HD*HIDN];    // Wo^T
__device__ float g_q   [(size_t)BB*SS*NH*HD];   // rna'd by rope
__device__ float g_k   [(size_t)BB*SS*NG*HD];   // rna'd by rope
__device__ float g_v   [(size_t)BB*SS*NG*HD];
__device__ float g_attn[(size_t)BB*SS*NH*HD];   // rna'd in attn epilogue

// ======================= helpers ============================================
__device__ __forceinline__ uint32_t smem_u32(const void* p) {
    uint32_t a;
    asm("{ .reg .u64 t; cvta.to.shared.u64 t, %1; cvt.u32.u64 %0, t; }"
        : "=r"(a) : "l"(p));
    return a;
}
__device__ __forceinline__ float rna_tf32(float v) {
    uint32_t r;
    asm("cvt.rna.tf32.f32 %0, %1;" : "=r"(r) : "f"(v));
    return __uint_as_float(r);
}
__device__ __forceinline__ void cp_async16(uint32_t daddr, const void* gptr) {
    asm volatile("cp.async.cg.shared.global [%0], [%1], 16;"
                 :: "r"(daddr), "l"(gptr) : "memory");
}
#define CP_COMMIT() asm volatile("cp.async.commit_group;" ::: "memory")
#define CP_WAIT(n)  asm volatile("cp.async.wait_group %0;" :: "n"(n) : "memory")

__device__ __forceinline__ void mma_tf32(float& d0, float& d1, float& d2, float& d3,
                                         uint32_t a0, uint32_t a1, uint32_t a2, uint32_t a3,
                                         uint32_t b0, uint32_t b1) {
    asm volatile(
        "mma.sync.aligned.m16n8k8.row.col.f32.tf32.tf32.f32 "
        "{%0,%1,%2,%3}, {%4,%5,%6,%7}, {%8,%9}, {%0,%1,%2,%3};"
        : "+f"(d0), "+f"(d1), "+f"(d2), "+f"(d3)
        : "r"(a0), "r"(a1), "r"(a2), "r"(a3), "r"(b0), "r"(b1));
}

// ======================= tf32 mma.sync GEMM v2 ==============================
// C[M, N_total] = A[M, K] (row-major) @ B^T, B stored [N_total, K] K-major.
// CTA tile 128x128x16, 256 threads (8 warps 2x4), warp tile 64x32.
// 4-stage cp.async pipeline, ONE __syncthreads per k-iter.
#define SROW 20
#define GSTG 4
#define GST_F (128 * SROW)                     // floats per stage per matrix
#define GEMM_SMEM (GSTG * GST_F * 2 * 4)       // bytes

__global__ void __launch_bounds__(256) gemm_mma(const float* __restrict__ A,
                                                const float* __restrict__ B,
                                                float* __restrict__ C,
                                                int N_total, int K)
{
    extern __shared__ float gsm[];
    float* Asm = gsm;
    float* Bsm = gsm + GSTG * GST_F;

    const int tid  = threadIdx.x;
    const int lane = tid & 31;
    const int wid  = tid >> 5;
    const int warpM = wid >> 2;
    const int warpN = wid & 3;
    const int r0 = lane >> 2;
    const int c0 = lane & 3;

    const int bm0 = blockIdx.y * 128;
    const int bn0 = blockIdx.x * 128;

    float acc[4][4][4];
#pragma unroll
    for (int mt = 0; mt < 4; mt++)
#pragma unroll
        for (int nt = 0; nt < 4; nt++)
#pragma unroll
            for (int r = 0; r < 4; r++) acc[mt][nt][r] = 0.f;

    const int nkt = K / 16;

    auto load_tiles = [&](int stg, int k0) {
#pragma unroll
        for (int i = 0; i < 2; i++) {
            int ch  = tid + i * 256;
            int row = ch >> 2;
            int off = (ch & 3) * 4;
            cp_async16(smem_u32(&Asm[stg * GST_F + row * SROW + off]),
                       &A[(size_t)(bm0 + row) * K + k0 + off]);
            cp_async16(smem_u32(&Bsm[stg * GST_F + row * SROW + off]),
                       &B[(size_t)(bn0 + row) * K + k0 + off]);
        }
    };

    // prologue: stages 0..2, one commit group each
#pragma unroll
    for (int s = 0; s < 3; s++) { load_tiles(s, s * 16); CP_COMMIT(); }

    for (int t = 0; t < nkt; t++) {
        CP_WAIT(2);              // group t complete (one group committed per iter)
        __syncthreads();         // data visible to all; prev readers of this buf done

        const float* Ab = &Asm[(t & 3) * GST_F];
        const float* Bb = &Bsm[(t & 3) * GST_F];
#pragma unroll
        for (int k8 = 0; k8 < 2; k8++) {
            uint32_t af[4][4];
#pragma unroll
            for (int mt = 0; mt < 4; mt++) {
                int row = warpM * 64 + mt * 16;
                int kk  = k8 * 8 + c0;
                af[mt][0] = __float_as_uint(Ab[(row + r0)     * SROW + kk]);
                af[mt][1] = __float_as_uint(Ab[(row + r0 + 8) * SROW + kk]);
                af[mt][2] = __float_as_uint(Ab[(row + r0)     * SROW + kk + 4]);
                af[mt][3] = __float_as_uint(Ab[(row + r0 + 8) * SROW + kk + 4]);
            }
            uint32_t bf[4][2];
#pragma unroll
            for (int nt = 0; nt < 4; nt++) {
                int col = warpN * 32 + nt * 8;
                int kk  = k8 * 8 + c0;
                bf[nt][0] = __float_as_uint(Bb[(col + r0) * SROW + kk]);
                bf[nt][1] = __float_as_uint(Bb[(col + r0) * SROW + kk + 4]);
            }
#pragma unroll
            for (int mt = 0; mt < 4; mt++)
#pragma unroll
                for (int nt = 0; nt < 4; nt++)
                    mma_tf32(acc[mt][nt][0], acc[mt][nt][1],
                             acc[mt][nt][2], acc[mt][nt][3],
                             af[mt][0], af[mt][1], af[mt][2], af[mt][3],
                             bf[nt][0], bf[nt][1]);
        }

        // prefetch stage t+3 (overwrites buffer (t-1)&3, already drained by the sync)
        if (t + 3 < nkt) load_tiles((t + 3) & 3, (t + 3) * 16);
        CP_COMMIT();             // commit EVERY iter (possibly empty) to keep counts aligned
    }

#pragma unroll
    for (int mt = 0; mt < 4; mt++) {
        int row = bm0 + warpM * 64 + mt * 16 + r0;
#pragma unroll
        for (int nt = 0; nt < 4; nt++) {
            int col = bn0 + warpN * 32 + nt * 8 + c0 * 2;
            float2 v0 = make_float2(acc[mt][nt][0], acc[mt][nt][1]);
            float2 v1 = make_float2(acc[mt][nt][2], acc[mt][nt][3]);
            *(float2*)&C[(size_t)row * N_total + col]       = v0;
            *(float2*)&C[(size_t)(row + 8) * N_total + col] = v1;
        }
    }
}

// ======================= prep kernels =======================================
__global__ void __launch_bounds__(256) round_tf32_kernel(const float4* __restrict__ in,
                                                         float4* __restrict__ out, int n4)
{
    int i = blockIdx.x * blockDim.x + threadIdx.x;
    if (i < n4) {
        float4 v = in[i];
        v.x = rna_tf32(v.x); v.y = rna_tf32(v.y);
        v.z = rna_tf32(v.z); v.w = rna_tf32(v.w);
        out[i] = v;
    }
}

__global__ void __launch_bounds__(256) transpose_rna_kernel(const float* __restrict__ in,
                                                            float* __restrict__ out,
                                                            int K, int N)
{
    __shared__ float t[32][33];
    int n0 = blockIdx.x * 32, k0 = blockIdx.y * 32;
    int x = threadIdx.x, y = threadIdx.y;
#pragma unroll
    for (int j = 0; j < 32; j += 8)
        t[y + j][x] = in[(size_t)(k0 + y + j) * N + n0 + x];
    __syncthreads();
#pragma unroll
    for (int j = 0; j < 32; j += 8)
        out[(size_t)(n0 + y + j) * K + k0 + x] = rna_tf32(t[x][y + j]);
}

// ---------------- RoPE (in place, rna outputs for tf32 consumers) -----------
__global__ void __launch_bounds__(256) rope_kernel(const float* __restrict__ cosb,
                                                   const float* __restrict__ sinb)
{
    int idx = blockIdx.x * blockDim.x + threadIdx.x;
    int p    = idx & 63;
    int rest = idx >> 6;
    int head = rest % (NH + NG);
    int bs   = rest / (NH + NG);
    int s    = bs & (SS - 1);

    float c  = cosb[s * HD + p];
    float sn = sinb[s * HD + p];

    float* buf;
    size_t base;
    if (head < NH) { buf = g_q; base = (size_t)bs * (NH * HD) + head * HD; }
    else           { buf = g_k; base = (size_t)bs * (NG * HD) + (head - NH) * HD; }

    float x0 = buf[base + p];
    float x1 = buf[base + p + 64];
    buf[base + p]      = rna_tf32(x0 * c - x1 * sn);
    buf[base + p + 64] = rna_tf32(x1 * c + x0 * sn);
}

// ======================= flash attention v2 (register softmax) ==============
// CTA: 128 q rows, 64-col K tiles, 256 threads = 8 warps (m16 slab each).
#define AQP 132
#define ASP 68
#define A_QS   0
#define A_KS   (A_QS + 128 * AQP)
#define A_VS   (A_KS + 64 * AQP)
#define A_SS   (A_VS + 64 * AQP)
#define ATTN_SMEM ((A_SS + 128 * ASP) * 4)

__global__ void __launch_bounds__(256) attn_mma_kernel()
{
    extern __shared__ float sm[];
    float* Qs = sm + A_QS;
    float* Ks = sm + A_KS;
    float* Vs = sm + A_VS;
    float* Ss = sm + A_SS;

    const int tid  = threadIdx.x;
    const int lane = tid & 31;
    const int wid  = tid >> 5;
    const int r0   = lane >> 2;
    const int c0   = lane & 3;
    const int slab = wid * 16;

    const int qt = gridDim.x - 1 - blockIdx.x;   // big tiles first
    const int h  = blockIdx.y;
    const int b  = blockIdx.z;
    const int g  = h >> 2;
    const float scale = 0.08838834764831845f;
    const int qrow0 = qt * 128;
    const int grow0 = b * SS + qrow0;

#pragma unroll
    for (int i = 0; i < 16; i++) {
        int l = i * 1024 + tid * 4;
        int r = l >> 7, c = l & 127;
        *(float4*)&Qs[r * AQP + c] =
            *(const float4*)&g_q[(size_t)(grow0 + r) * (NH * HD) + h * HD + c];
    }

    // per-thread online-softmax state for rows ra=slab+r0, rb=ra+8
    float m_a = -INFINITY, m_b = -INFINITY;
    float l_a = 0.f,       l_b = 0.f;

    float o[16][4];
#pragma unroll
    for (int nt = 0; nt < 16; nt++)
#pragma unroll
        for (int r = 0; r < 4; r++) o[nt][r] = 0.f;

    const int nkt = 2 * qt + 2;

    for (int kt = 0; kt < nkt; kt++) {
        __syncthreads();                 // prev-iter K/V readers done
        const int krow0 = b * SS + kt * 64;
#pragma unroll
        for (int i = 0; i < 8; i++) {
            int l = i * 1024 + tid * 4;
            int r = l >> 7, c = l & 127;
            size_t goff = (size_t)(krow0 + r) * (NG * HD) + g * HD + c;
            *(float4*)&Ks[r * AQP + c] = *(const float4*)&g_k[goff];
            float4 v = *(const float4*)&g_v[goff];
            v.x = rna_tf32(v.x); v.y = rna_tf32(v.y);
            v.z = rna_tf32(v.z); v.w = rna_tf32(v.w);
            *(float4*)&Vs[r * AQP + c] = v;
        }
        __syncthreads();

        // ---- QK^T : 16 rows x 64 cols, K=128 ----
        float sacc[8][4];
#pragma unroll
        for (int nt = 0; nt < 8; nt++)
#pragma unroll
            for (int r = 0; r < 4; r++) sacc[nt][r] = 0.f;

#pragma unroll
        for (int k8 = 0; k8 < 16; k8++) {
            int kk = k8 * 8 + c0;
            uint32_t a0 = __float_as_uint(Qs[(slab + r0)     * AQP + kk]);
            uint32_t a1 = __float_as_uint(Qs[(slab + r0 + 8) * AQP + kk]);
            uint32_t a2 = __float_as_uint(Qs[(slab + r0)     * AQP + kk + 4]);
            uint32_t a3 = __float_as_uint(Qs[(slab + r0 + 8) * AQP + kk + 4]);
#pragma unroll
            for (int nt = 0; nt < 8; nt++) {
                uint32_t b0 = __float_as_uint(Ks[(nt * 8 + r0) * AQP + kk]);
                uint32_t b1 = __float_as_uint(Ks[(nt * 8 + r0) * AQP + kk + 4]);
                mma_tf32(sacc[nt][0], sacc[nt][1], sacc[nt][2], sacc[nt][3],
                         a0, a1, a2, a3, b0, b1);
            }
        }

        // ---- scale + causal mask (registers) ----
        const int rg_a = qrow0 + slab + r0;
        const int rg_b = rg_a + 8;
#pragma unroll
        for (int nt = 0; nt < 8; nt++) {
            int cg = kt * 64 + nt * 8 + 2 * c0;
            sacc[nt][0] = (cg     > rg_a) ? -1e30f : sacc[nt][0] * scale;
            sacc[nt][1] = (cg + 1 > rg_a) ? -1e30f : sacc[nt][1] * scale;
            sacc[nt][2] = (cg     > rg_b) ? -1e30f : sacc[nt][2] * scale;
            sacc[nt][3] = (cg + 1 > rg_b) ? -1e30f : sacc[nt][3] * scale;
        }

        // ---- row max via quad shuffle (lanes sharing a row differ in bits 0,1) --
        float mx_a = -INFINITY, mx_b = -INFINITY;
#pragma unroll
        for (int nt = 0; nt < 8; nt++) {
            mx_a = fmaxf(mx_a, fmaxf(sacc[nt][0], sacc[nt][1]));
            mx_b = fmaxf(mx_b, fmaxf(sacc[nt][2], sacc[nt][3]));
        }
        mx_a = fmaxf(mx_a, __shfl_xor_sync(0xffffffffu, mx_a, 1));
        mx_a = fmaxf(mx_a, __shfl_xor_sync(0xffffffffu, mx_a, 2));
        mx_b = fmaxf(mx_b, __shfl_xor_sync(0xffffffffu, mx_b, 1));
        mx_b = fmaxf(mx_b, __shfl_xor_sync(0xffffffffu, mx_b, 2));

        float mnew_a = fmaxf(m_a, mx_a);
        float mnew_b = fmaxf(m_b, mx_b);
        float alpha_a = __expf(m_a - mnew_a);
        float alpha_b = __expf(m_b - mnew_b);
        m_a = mnew_a; m_b = mnew_b;

        // ---- exp + partial sums, write P to own rows of Ss ----
        float ps_a = 0.f, ps_b = 0.f;
#pragma unroll
        for (int nt = 0; nt < 8; nt++) {
            float e0 = __expf(sacc[nt][0] - m_a);
            float e1 = __expf(sacc[nt][1] - m_a);
            float e2 = __expf(sacc[nt][2] - m_b);
            float e3 = __expf(sacc[nt][3] - m_b);
            ps_a += e0 + e1;
            ps_b += e2 + e3;
            *(float2*)&Ss[(slab + r0) * ASP + nt * 8 + 2 * c0] =
                make_float2(rna_tf32(e0), rna_tf32(e1));
            *(float2*)&Ss[(slab + r0 + 8) * ASP + nt * 8 + 2 * c0] =
                make_float2(rna_tf32(e2), rna_tf32(e3));
        }
        ps_a += __shfl_xor_sync(0xffffffffu, ps_a, 1);
        ps_a += __shfl_xor_sync(0xffffffffu, ps_a, 2);
        ps_b += __shfl_xor_sync(0xffffffffu, ps_b, 1);
        ps_b += __shfl_xor_sync(0xffffffffu, ps_b, 2);
        l_a = l_a * alpha_a + ps_a;
        l_b = l_b * alpha_b + ps_b;

        // ---- rescale O ----
#pragma unroll
        for (int nt = 0; nt < 16; nt++) {
            o[nt][0] *= alpha_a; o[nt][1] *= alpha_a;
            o[nt][2] *= alpha_b; o[nt][3] *= alpha_b;
        }

        __syncwarp();    // own-row P stores visible to own warp's loads

        // ---- P @ V : M=16, N=128, K=64; warp reads ONLY its own Ss rows ----
#pragma unroll
        for (int k8 = 0; k8 < 8; k8++) {
            int kk = k8 * 8 + c0;
            uint32_t a0 = __float_as_uint(Ss[(slab + r0)     * ASP + kk]);
            uint32_t a1 = __float_as_uint(Ss[(slab + r0 + 8) * ASP + kk]);
            uint32_t a2 = __float_as_uint(Ss[(slab + r0)     * ASP + kk + 4]);
            uint32_t a3 = __float_as_uint(Ss[(slab + r0 + 8) * ASP + kk + 4]);
#pragma unroll
            for (int nt = 0; nt < 16; nt++) {
                uint32_t b0 = __float_as_uint(Vs[kk * AQP + nt * 8 + r0]);
                uint32_t b1 = __float_as_uint(Vs[(kk + 4) * AQP + nt * 8 + r0]);
                mma_tf32(o[nt][0], o[nt][1], o[nt][2], o[nt][3],
                         a0, a1, a2, a3, b0, b1);
            }
        }
    }

    // ---- epilogue: normalize, rna, store ----
    float la = 1.f / l_a;
    float lb = 1.f / l_b;
    const size_t rowa = (size_t)(grow0 + slab + r0) * (NH * HD) + h * HD;
    const size_t rowb = (size_t)(grow0 + slab + r0 + 8) * (NH * HD) + h * HD;
#pragma unroll
    for (int nt = 0; nt < 16; nt++) {
        int c = nt * 8 + 2 * c0;
        float2 v0 = make_float2(rna_tf32(o[nt][0] * la), rna_tf32(o[nt][1] * la));
        float2 v1 = make_float2(rna_tf32(o[nt][2] * lb), rna_tf32(o[nt][3] * lb));
        *(float2*)&g_attn[rowa + c] = v0;
        *(float2*)&g_attn[rowb + c] = v1;
    }
}

// ======================= host side ==========================================
extern "C" void kernel_launch(void* const* d_in, const int* in_sizes, int n_in,
                              void* d_out, int out_size)
{
    const float* x    = (const float*)d_in[0];
    const float* cosb = (const float*)d_in[1];
    const float* sinb = (const float*)d_in[2];
    const float* Wq   = (const float*)d_in[3];
    const float* Wk   = (const float*)d_in[4];
    const float* Wv   = (const float*)d_in[5];
    const float* Wo   = (const float*)d_in[6];
    float* out = (float*)d_out;

    float *xt, *wqt, *wkt, *wvt, *wot, *qp, *kp, *vp, *ap;
    cudaGetSymbolAddress((void**)&xt,  g_xt);
    cudaGetSymbolAddress((void**)&wqt, g_wqt);
    cudaGetSymbolAddress((void**)&wkt, g_wkt);
    cudaGetSymbolAddress((void**)&wvt, g_wvt);
    cudaGetSymbolAddress((void**)&wot, g_wot);
    cudaGetSymbolAddress((void**)&qp,  g_q);
    cudaGetSymbolAddress((void**)&kp,  g_k);
    cudaGetSymbolAddress((void**)&vp,  g_v);
    cudaGetSymbolAddress((void**)&ap,  g_attn);

    const int M = BB * SS;       // 4096

    cudaFuncSetAttribute(gemm_mma, cudaFuncAttributeMaxDynamicSharedMemorySize, GEMM_SMEM);
    cudaFuncSetAttribute(attn_mma_kernel, cudaFuncAttributeMaxDynamicSharedMemorySize,
                         ATTN_SMEM);

    // 1) rna(x), weight transposes (+rna)
    int n4 = M * HIDN / 4;
    round_tf32_kernel<<<(n4 + 255) / 256, 256>>>((const float4*)x, (float4*)xt, n4);
    transpose_rna_kernel<<<dim3((NH * HD) / 32, HIDN / 32), dim3(32, 8)>>>(Wq, wqt, HIDN, NH * HD);
    transpose_rna_kernel<<<dim3((NG * HD) / 32, HIDN / 32), dim3(32, 8)>>>(Wk, wkt, HIDN, NG * HD);
    transpose_rna_kernel<<<dim3((NG * HD) / 32, HIDN / 32), dim3(32, 8)>>>(Wv, wvt, HIDN, NG * HD);
    transpose_rna_kernel<<<dim3(HIDN / 32, (NH * HD) / 32), dim3(32, 8)>>>(Wo, wot, NH * HD, HIDN);

    // 2) QKV projections (tf32 mma.sync, 4-stage pipeline)
    gemm_mma<<<dim3((NH * HD) / 128, M / 128), 256, GEMM_SMEM>>>(xt, wqt, qp, NH * HD, HIDN);
    gemm_mma<<<dim3((NG * HD) / 128, M / 128), 256, GEMM_SMEM>>>(xt, wkt, kp, NG * HD, HIDN);
    gemm_mma<<<dim3((NG * HD) / 128, M / 128), 256, GEMM_SMEM>>>(xt, wvt, vp, NG * HD, HIDN);

    // 3) RoPE (+rna)
    int nrope = BB * SS * (NH + NG) * 64;
    rope_kernel<<<nrope / 256, 256>>>(cosb, sinb);

    // 4) attention (tf32 mma flash, register softmax)
    attn_mma_kernel<<<dim3(SS / 128, NH, BB), 256, ATTN_SMEM>>>();

    // 5) output projection
    gemm_mma<<<dim3(HIDN / 128, M / 128), 256, GEMM_SMEM>>>(ap, wot, out, HIDN, NH * HD);
}

// round 8
// speedup vs baseline: 7.0273x; 2.0396x over previous
#include <cuda_runtime.h>
#include <cuda_fp16.h>
#include <math.h>
#include <stdint.h>

#define BB  2
#define SS  2048
#define HIDN 2048
#define NH  16
#define NG  4
#define HD  128

// ---------------- scratch (static device globals; no allocs) ----------------
__device__ __half g_xh  [(size_t)BB*SS*HIDN];    // half(x)
__device__ __half g_wqth[(size_t)HIDN*NH*HD];    // Wq^T [N,K] half
__device__ __half g_wkth[(size_t)HIDN*NG*HD];
__device__ __half g_wvth[(size_t)HIDN*NG*HD];
__device__ __half g_woth[(size_t)NH*HD*HIDN];    // Wo^T half
__device__ __half g_qh  [(size_t)BB*SS*NH*HD];   // gemm out (half), rope in-place
__device__ __half g_kh  [(size_t)BB*SS*NG*HD];
__device__ __half g_vh  [(size_t)BB*SS*NG*HD];
__device__ __half g_attnh[(size_t)BB*SS*NH*HD];  // attn out (half)

// ======================= helpers ============================================
__device__ __forceinline__ uint32_t smem_u32(const void* p) {
    uint32_t a;
    asm("{ .reg .u64 t; cvta.to.shared.u64 t, %1; cvt.u32.u64 %0, t; }"
        : "=r"(a) : "l"(p));
    return a;
}
__device__ __forceinline__ void cp_async16(uint32_t daddr, const void* gptr) {
    asm volatile("cp.async.cg.shared.global [%0], [%1], 16;"
                 :: "r"(daddr), "l"(gptr) : "memory");
}
#define CP_COMMIT() asm volatile("cp.async.commit_group;" ::: "memory")
#define CP_WAIT(n)  asm volatile("cp.async.wait_group %0;" :: "n"(n) : "memory")

__device__ __forceinline__ void mma_f16(float& d0, float& d1, float& d2, float& d3,
                                        uint32_t a0, uint32_t a1, uint32_t a2, uint32_t a3,
                                        uint32_t b0, uint32_t b1) {
    asm volatile(
        "mma.sync.aligned.m16n8k16.row.col.f32.f16.f16.f32 "
        "{%0,%1,%2,%3}, {%4,%5,%6,%7}, {%8,%9}, {%0,%1,%2,%3};"
        : "+f"(d0), "+f"(d1), "+f"(d2), "+f"(d3)
        : "r"(a0), "r"(a1), "r"(a2), "r"(a3), "r"(b0), "r"(b1));
}
__device__ __forceinline__ void ldsm_x4(uint32_t& r0, uint32_t& r1,
                                        uint32_t& r2, uint32_t& r3, uint32_t addr) {
    asm volatile("ldmatrix.sync.aligned.m8n8.x4.shared.b16 {%0,%1,%2,%3}, [%4];"
                 : "=r"(r0), "=r"(r1), "=r"(r2), "=r"(r3) : "r"(addr));
}
__device__ __forceinline__ void ldsm_x4_t(uint32_t& r0, uint32_t& r1,
                                          uint32_t& r2, uint32_t& r3, uint32_t addr) {
    asm volatile("ldmatrix.sync.aligned.m8n8.x4.trans.shared.b16 {%0,%1,%2,%3}, [%4];"
                 : "=r"(r0), "=r"(r1), "=r"(r2), "=r"(r3) : "r"(addr));
}

// ======================= fp16 mma.sync GEMM =================================
// C[M, N_total] = A[M, K] (half, row-major) @ B^T (B [N_total, K] half K-major).
// CTA tile 128x128x32(half), 256 threads (8 warps 2x4), warp tile 64x32.
// 4-stage cp.async pipeline, one __syncthreads per k-chunk, ldmatrix fragments.
#define SROWH 40                         // smem row stride in halves (80B)
#define GSTG  4
#define GST_H (128 * SROWH)              // halves per stage per matrix
#define GEMM_SMEM (GSTG * GST_H * 2 * 2) // 81920 bytes

template<int OUT_HALF>
__global__ void __launch_bounds__(256) gemm_mma_h(const __half* __restrict__ A,
                                                  const __half* __restrict__ B,
                                                  void* __restrict__ Cv,
                                                  int N_total, int K)
{
    extern __shared__ __half gsmh[];
    __half* Asm = gsmh;
    __half* Bsm = gsmh + GSTG * GST_H;

    const int tid  = threadIdx.x;
    const int lane = tid & 31;
    const int wid  = tid >> 5;
    const int warpM = wid >> 2;
    const int warpN = wid & 3;
    const int r0 = lane >> 2;
    const int c0 = lane & 3;
    const int lr = lane & 7;             // ldmatrix row within tile
    const int lg = lane >> 3;            // ldmatrix tile group 0..3

    const int bm0 = blockIdx.y * 128;
    const int bn0 = blockIdx.x * 128;

    float acc[4][4][4];
#pragma unroll
    for (int mt = 0; mt < 4; mt++)
#pragma unroll
        for (int nt = 0; nt < 4; nt++)
#pragma unroll
            for (int r = 0; r < 4; r++) acc[mt][nt][r] = 0.f;

    const int nkt = K / 32;              // 32-half chunks

    auto load_tiles = [&](int stg, int k0) {
#pragma unroll
        for (int i = 0; i < 2; i++) {
            int ch  = tid + i * 256;     // 0..511
            int row = ch >> 2;
            int off = (ch & 3) * 8;      // halves
            cp_async16(smem_u32(&Asm[stg * GST_H + row * SROWH + off]),
                       &A[(size_t)(bm0 + row) * K + k0 + off]);
            cp_async16(smem_u32(&Bsm[stg * GST_H + row * SROWH + off]),
                       &B[(size_t)(bn0 + row) * K + k0 + off]);
        }
    };

#pragma unroll
    for (int s = 0; s < 3; s++) { load_tiles(s, s * 32); CP_COMMIT(); }

    for (int t = 0; t < nkt; t++) {
        CP_WAIT(2);
        __syncthreads();

        const __half* Ab = &Asm[(t & 3) * GST_H];
        const __half* Bb = &Bsm[(t & 3) * GST_H];
#pragma unroll
        for (int k16 = 0; k16 < 2; k16++) {
            const int kk0 = k16 * 16;
            uint32_t af[4][4];
#pragma unroll
            for (int mt = 0; mt < 4; mt++) {
                uint32_t addr = smem_u32(&Ab[(warpM * 64 + mt * 16 + (lg & 1) * 8 + lr) * SROWH
                                             + kk0 + (lg >> 1) * 8]);
                ldsm_x4(af[mt][0], af[mt][1], af[mt][2], af[mt][3], addr);
            }
            uint32_t bf[2][4];
#pragma unroll
            for (int np = 0; np < 2; np++) {
                uint32_t addr = smem_u32(&Bb[(warpN * 32 + np * 16 + (lg >> 1) * 8 + lr) * SROWH
                                             + kk0 + (lg & 1) * 8]);
                ldsm_x4(bf[np][0], bf[np][1], bf[np][2], bf[np][3], addr);
            }
#pragma unroll
            for (int mt = 0; mt < 4; mt++)
#pragma unroll
                for (int nt = 0; nt < 4; nt++)
                    mma_f16(acc[mt][nt][0], acc[mt][nt][1],
                            acc[mt][nt][2], acc[mt][nt][3],
                            af[mt][0], af[mt][1], af[mt][2], af[mt][3],
                            bf[nt >> 1][(nt & 1) * 2], bf[nt >> 1][(nt & 1) * 2 + 1]);
        }

        if (t + 3 < nkt) load_tiles((t + 3) & 3, (t + 3) * 32);
        CP_COMMIT();
    }

#pragma unroll
    for (int mt = 0; mt < 4; mt++) {
        int row = bm0 + warpM * 64 + mt * 16 + r0;
#pragma unroll
        for (int nt = 0; nt < 4; nt++) {
            int col = bn0 + warpN * 32 + nt * 8 + c0 * 2;
            if (OUT_HALF) {
                __half* C = (__half*)Cv;
                *(half2*)&C[(size_t)row * N_total + col] =
                    __floats2half2_rn(acc[mt][nt][0], acc[mt][nt][1]);
                *(half2*)&C[(size_t)(row + 8) * N_total + col] =
                    __floats2half2_rn(acc[mt][nt][2], acc[mt][nt][3]);
            } else {
                float* C = (float*)Cv;
                *(float2*)&C[(size_t)row * N_total + col] =
                    make_float2(acc[mt][nt][0], acc[mt][nt][1]);
                *(float2*)&C[(size_t)(row + 8) * N_total + col] =
                    make_float2(acc[mt][nt][2], acc[mt][nt][3]);
            }
        }
    }
}

// ======================= prep kernels =======================================
// float -> half elementwise (4 per thread)
__global__ void __launch_bounds__(256) conv_h_kernel(const float4* __restrict__ in,
                                                     __half* __restrict__ out, int n4)
{
    int i = blockIdx.x * blockDim.x + threadIdx.x;
    if (i < n4) {
        float4 v = in[i];
        half2 h0 = __floats2half2_rn(v.x, v.y);
        half2 h1 = __floats2half2_rn(v.z, v.w);
        *(uint2*)&out[i * 4] = make_uint2(*(uint32_t*)&h0, *(uint32_t*)&h1);
    }
}

// out[n, k] = half(in[k, n]); in is [K, N] row-major float
__global__ void __launch_bounds__(256) transpose_h_kernel(const float* __restrict__ in,
                                                          __half* __restrict__ out,
                                                          int K, int N)
{
    __shared__ float t[32][33];
    int n0 = blockIdx.x * 32, k0 = blockIdx.y * 32;
    int x = threadIdx.x, y = threadIdx.y;
#pragma unroll
    for (int j = 0; j < 32; j += 8)
        t[y + j][x] = in[(size_t)(k0 + y + j) * N + n0 + x];
    __syncthreads();
#pragma unroll
    for (int j = 0; j < 32; j += 8)
        out[(size_t)(n0 + y + j) * K + k0 + x] = __float2half(t[x][y + j]);
}

// ---------------- RoPE (in place on half q/k) -------------------------------
__global__ void __launch_bounds__(256) rope_kernel(const float* __restrict__ cosb,
                                                   const float* __restrict__ sinb)
{
    int idx = blockIdx.x * blockDim.x + threadIdx.x;
    int p    = idx & 63;
    int rest = idx >> 6;
    int head = rest % (NH + NG);
    int bs   = rest / (NH + NG);
    int s    = bs & (SS - 1);

    float c  = cosb[s * HD + p];
    float sn = sinb[s * HD + p];

    __half* buf;
    size_t base;
    if (head < NH) { buf = g_qh; base = (size_t)bs * (NH * HD) + head * HD; }
    else           { buf = g_kh; base = (size_t)bs * (NG * HD) + (head - NH) * HD; }

    float x0 = __half2float(buf[base + p]);
    float x1 = __half2float(buf[base + p + 64]);
    buf[base + p]      = __float2half(x0 * c - x1 * sn);
    buf[base + p + 64] = __float2half(x1 * c + x0 * sn);
}

// ======================= flash attention (fp16 mma) =========================
// CTA: 128 q rows, 64-token K tiles, 256 threads = 8 warps (m16 slab each).
#define AQPH 136                        // Q/K/V row stride (halves, 272B)
#define SSPH 72                         // P row stride (halves, 144B)
#define AH_QS 0
#define AH_KS (AH_QS + 128 * AQPH)
#define AH_VS (AH_KS + 64 * AQPH)
#define AH_SS (AH_VS + 64 * AQPH)
#define ATTN_SMEM ((AH_SS + 128 * SSPH) * 2)

__global__ void __launch_bounds__(256) attn_mma_kernel()
{
    extern __shared__ __half smh[];
    __half* Qs = smh + AH_QS;
    __half* Ks = smh + AH_KS;
    __half* Vs = smh + AH_VS;
    __half* Ss = smh + AH_SS;

    const int tid  = threadIdx.x;
    const int lane = tid & 31;
    const int wid  = tid >> 5;
    const int r0   = lane >> 2;
    const int c0   = lane & 3;
    const int lr   = lane & 7;
    const int lg   = lane >> 3;
    const int slab = wid * 16;

    const int qt = gridDim.x - 1 - blockIdx.x;   // big tiles first
    const int h  = blockIdx.y;
    const int b  = blockIdx.z;
    const int g  = h >> 2;
    const float scale = 0.08838834764831845f;
    const int qrow0 = qt * 128;
    const int grow0 = b * SS + qrow0;

    // ---- load Q tile (half, 16B chunks) ----
#pragma unroll
    for (int i = 0; i < 8; i++) {
        int ch = i * 256 + tid;          // 0..2047
        int r = ch >> 4, c8 = (ch & 15) * 8;
        *(uint4*)&Qs[r * AQPH + c8] =
            *(const uint4*)&g_qh[(size_t)(grow0 + r) * (NH * HD) + h * HD + c8];
    }

    float m_a = -INFINITY, m_b = -INFINITY;
    float l_a = 0.f,       l_b = 0.f;

    float o[16][4];
#pragma unroll
    for (int nt = 0; nt < 16; nt++)
#pragma unroll
        for (int r = 0; r < 4; r++) o[nt][r] = 0.f;

    const int nkt = 2 * qt + 2;

    for (int kt = 0; kt < nkt; kt++) {
        __syncthreads();
        const int krow0 = b * SS + kt * 64;
#pragma unroll
        for (int i = 0; i < 4; i++) {
            int ch = i * 256 + tid;      // 0..1023
            int r = ch >> 4, c8 = (ch & 15) * 8;
            size_t goff = (size_t)(krow0 + r) * (NG * HD) + g * HD + c8;
            *(uint4*)&Ks[r * AQPH + c8] = *(const uint4*)&g_kh[goff];
            *(uint4*)&Vs[r * AQPH + c8] = *(const uint4*)&g_vh[goff];
        }
        __syncthreads();

        // ---- QK^T : 16 rows x 64 cols, K=128 (8 k16 steps) ----
        float sacc[8][4];
#pragma unroll
        for (int nt = 0; nt < 8; nt++)
#pragma unroll
            for (int r = 0; r < 4; r++) sacc[nt][r] = 0.f;

#pragma unroll
        for (int k16 = 0; k16 < 8; k16++) {
            const int kk0 = k16 * 16;
            uint32_t a0, a1, a2, a3;
            ldsm_x4(a0, a1, a2, a3,
                    smem_u32(&Qs[(slab + (lg & 1) * 8 + lr) * AQPH + kk0 + (lg >> 1) * 8]));
            uint32_t bf[4][4];
#pragma unroll
            for (int np = 0; np < 4; np++)
                ldsm_x4(bf[np][0], bf[np][1], bf[np][2], bf[np][3],
                        smem_u32(&Ks[(np * 16 + (lg >> 1) * 8 + lr) * AQPH + kk0 + (lg & 1) * 8]));
#pragma unroll
            for (int nt = 0; nt < 8; nt++)
                mma_f16(sacc[nt][0], sacc[nt][1], sacc[nt][2], sacc[nt][3],
                        a0, a1, a2, a3,
                        bf[nt >> 1][(nt & 1) * 2], bf[nt >> 1][(nt & 1) * 2 + 1]);
        }

        // ---- scale + causal mask ----
        const int rg_a = qrow0 + slab + r0;
        const int rg_b = rg_a + 8;
#pragma unroll
        for (int nt = 0; nt < 8; nt++) {
            int cg = kt * 64 + nt * 8 + 2 * c0;
            sacc[nt][0] = (cg     > rg_a) ? -1e30f : sacc[nt][0] * scale;
            sacc[nt][1] = (cg + 1 > rg_a) ? -1e30f : sacc[nt][1] * scale;
            sacc[nt][2] = (cg     > rg_b) ? -1e30f : sacc[nt][2] * scale;
            sacc[nt][3] = (cg + 1 > rg_b) ? -1e30f : sacc[nt][3] * scale;
        }

        // ---- row max via quad shuffle ----
        float mx_a = -INFINITY, mx_b = -INFINITY;
#pragma unroll
        for (int nt = 0; nt < 8; nt++) {
            mx_a = fmaxf(mx_a, fmaxf(sacc[nt][0], sacc[nt][1]));
            mx_b = fmaxf(mx_b, fmaxf(sacc[nt][2], sacc[nt][3]));
        }
        mx_a = fmaxf(mx_a, __shfl_xor_sync(0xffffffffu, mx_a, 1));
        mx_a = fmaxf(mx_a, __shfl_xor_sync(0xffffffffu, mx_a, 2));
        mx_b = fmaxf(mx_b, __shfl_xor_sync(0xffffffffu, mx_b, 1));
        mx_b = fmaxf(mx_b, __shfl_xor_sync(0xffffffffu, mx_b, 2));

        float mnew_a = fmaxf(m_a, mx_a);
        float mnew_b = fmaxf(m_b, mx_b);
        float alpha_a = __expf(m_a - mnew_a);
        float alpha_b = __expf(m_b - mnew_b);
        m_a = mnew_a; m_b = mnew_b;

        // ---- exp + partial sums, write P (half) to own rows ----
        float ps_a = 0.f, ps_b = 0.f;
#pragma unroll
        for (int nt = 0; nt < 8; nt++) {
            float e0 = __expf(sacc[nt][0] - m_a);
            float e1 = __expf(sacc[nt][1] - m_a);
            float e2 = __expf(sacc[nt][2] - m_b);
            float e3 = __expf(sacc[nt][3] - m_b);
            ps_a += e0 + e1;
            ps_b += e2 + e3;
            *(half2*)&Ss[(slab + r0) * SSPH + nt * 8 + 2 * c0]     = __floats2half2_rn(e0, e1);
            *(half2*)&Ss[(slab + r0 + 8) * SSPH + nt * 8 + 2 * c0] = __floats2half2_rn(e2, e3);
        }
        ps_a += __shfl_xor_sync(0xffffffffu, ps_a, 1);
        ps_a += __shfl_xor_sync(0xffffffffu, ps_a, 2);
        ps_b += __shfl_xor_sync(0xffffffffu, ps_b, 1);
        ps_b += __shfl_xor_sync(0xffffffffu, ps_b, 2);
        l_a = l_a * alpha_a + ps_a;
        l_b = l_b * alpha_b + ps_b;

#pragma unroll
        for (int nt = 0; nt < 16; nt++) {
            o[nt][0] *= alpha_a; o[nt][1] *= alpha_a;
            o[nt][2] *= alpha_b; o[nt][3] *= alpha_b;
        }

        __syncwarp();    // own-slab P stores visible to own warp's ldmatrix

        // ---- P @ V : M=16, N=128, K=64 tokens (4 k16 steps) ----
#pragma unroll
        for (int k16 = 0; k16 < 4; k16++) {
            const int kk = k16 * 16;
            uint32_t a0, a1, a2, a3;
            ldsm_x4(a0, a1, a2, a3,
                    smem_u32(&Ss[(slab + (lg & 1) * 8 + lr) * SSPH + kk + (lg >> 1) * 8]));
            uint32_t bf[8][4];
#pragma unroll
            for (int np = 0; np < 8; np++)
                ldsm_x4_t(bf[np][0], bf[np][1], bf[np][2], bf[np][3],
                          smem_u32(&Vs[(kk + (lg & 1) * 8 + lr) * AQPH + np * 16 + (lg >> 1) * 8]));
#pragma unroll
            for (int nt = 0; nt < 16; nt++)
                mma_f16(o[nt][0], o[nt][1], o[nt][2], o[nt][3],
                        a0, a1, a2, a3,
                        bf[nt >> 1][(nt & 1) * 2], bf[nt >> 1][(nt & 1) * 2 + 1]);
        }
    }

    // ---- epilogue: normalize, store half ----
    float la = 1.f / l_a;
    float lb = 1.f / l_b;
    const size_t rowa = (size_t)(grow0 + slab + r0) * (NH * HD) + h * HD;
    const size_t rowb = (size_t)(grow0 + slab + r0 + 8) * (NH * HD) + h * HD;
#pragma unroll
    for (int nt = 0; nt < 16; nt++) {
        int c = nt * 8 + 2 * c0;
        *(half2*)&g_attnh[rowa + c] = __floats2half2_rn(o[nt][0] * la, o[nt][1] * la);
        *(half2*)&g_attnh[rowb + c] = __floats2half2_rn(o[nt][2] * lb, o[nt][3] * lb);
    }
}

// ======================= host side ==========================================
extern "C" void kernel_launch(void* const* d_in, const int* in_sizes, int n_in,
                              void* d_out, int out_size)
{
    const float* x    = (const float*)d_in[0];
    const float* cosb = (const float*)d_in[1];
    const float* sinb = (const float*)d_in[2];
    const float* Wq   = (const float*)d_in[3];
    const float* Wk   = (const float*)d_in[4];
    const float* Wv   = (const float*)d_in[5];
    const float* Wo   = (const float*)d_in[6];
    float* out = (float*)d_out;

    __half *xh, *wqth, *wkth, *wvth, *woth, *qh, *kh, *vh, *ah;
    cudaGetSymbolAddress((void**)&xh,   g_xh);
    cudaGetSymbolAddress((void**)&wqth, g_wqth);
    cudaGetSymbolAddress((void**)&wkth, g_wkth);
    cudaGetSymbolAddress((void**)&wvth, g_wvth);
    cudaGetSymbolAddress((void**)&woth, g_woth);
    cudaGetSymbolAddress((void**)&qh,   g_qh);
    cudaGetSymbolAddress((void**)&kh,   g_kh);
    cudaGetSymbolAddress((void**)&vh,   g_vh);
    cudaGetSymbolAddress((void**)&ah,   g_attnh);

    const int M = BB * SS;       // 4096

    cudaFuncSetAttribute(gemm_mma_h<0>, cudaFuncAttributeMaxDynamicSharedMemorySize, GEMM_SMEM);
    cudaFuncSetAttribute(gemm_mma_h<1>, cudaFuncAttributeMaxDynamicSharedMemorySize, GEMM_SMEM);
    cudaFuncSetAttribute(attn_mma_kernel, cudaFuncAttributeMaxDynamicSharedMemorySize,
                         ATTN_SMEM);

    // 1) half(x), weight transposes (+half)
    int n4 = M * HIDN / 4;
    conv_h_kernel<<<(n4 + 255) / 256, 256>>>((const float4*)x, xh, n4);
    transpose_h_kernel<<<dim3((NH * HD) / 32, HIDN / 32), dim3(32, 8)>>>(Wq, wqth, HIDN, NH * HD);
    transpose_h_kernel<<<dim3((NG * HD) / 32, HIDN / 32), dim3(32, 8)>>>(Wk, wkth, HIDN, NG * HD);
    transpose_h_kernel<<<dim3((NG * HD) / 32, HIDN / 32), dim3(32, 8)>>>(Wv, wvth, HIDN, NG * HD);
    transpose_h_kernel<<<dim3(HIDN / 32, (NH * HD) / 32), dim3(32, 8)>>>(Wo, woth, NH * HD, HIDN);

    // 2) QKV projections (fp16 mma, half output)
    gemm_mma_h<1><<<dim3((NH * HD) / 128, M / 128), 256, GEMM_SMEM>>>(xh, wqth, qh, NH * HD, HIDN);
    gemm_mma_h<1><<<dim3((NG * HD) / 128, M / 128), 256, GEMM_SMEM>>>(xh, wkth, kh, NG * HD, HIDN);
    gemm_mma_h<1><<<dim3((NG * HD) / 128, M / 128), 256, GEMM_SMEM>>>(xh, wvth, vh, NG * HD, HIDN);

    // 3) RoPE (in place on half q/k)
    int nrope = BB * SS * (NH + NG) * 64;
    rope_kernel<<<nrope / 256, 256>>>(cosb, sinb);

    // 4) attention (fp16 mma flash)
    attn_mma_kernel<<<dim3(SS / 128, NH, BB), 256, ATTN_SMEM>>>();

    // 5) output projection (fp32 output)
    gemm_mma_h<0><<<dim3(HIDN / 128, M / 128), 256, GEMM_SMEM>>>(ah, woth, out, HIDN, NH * HD);
}

// round 9
// speedup vs baseline: 7.2233x; 1.0279x over previous
#include <cuda_runtime.h>
#include <cuda_fp16.h>
#include <math.h>
#include <stdint.h>

#define BB  2
#define SS  2048
#define HIDN 2048
#define NH  16
#define NG  4
#define HD  128
#define NQKV (NH * HD + 2 * NG * HD)     // 3072 fused output cols

// ---------------- scratch (static device globals; no allocs) ----------------
__device__ __half g_xh   [(size_t)BB*SS*HIDN];     // half(x)
__device__ __half g_wqkvt[(size_t)NQKV*HIDN];      // [Wq;Wk;Wv]^T [3072, 2048]
__device__ __half g_woth [(size_t)NH*HD*HIDN];     // Wo^T half
__device__ __half g_qkvh [(size_t)BB*SS*NQKV];     // fused qkv, rope in-place
__device__ __half g_attnh[(size_t)BB*SS*NH*HD];    // attn out (half)

// ======================= helpers ============================================
__device__ __forceinline__ uint32_t smem_u32(const void* p) {
    uint32_t a;
    asm("{ .reg .u64 t; cvta.to.shared.u64 t, %1; cvt.u32.u64 %0, t; }"
        : "=r"(a) : "l"(p));
    return a;
}
__device__ __forceinline__ void cp_async16(uint32_t daddr, const void* gptr) {
    asm volatile("cp.async.cg.shared.global [%0], [%1], 16;"
                 :: "r"(daddr), "l"(gptr) : "memory");
}
#define CP_COMMIT() asm volatile("cp.async.commit_group;" ::: "memory")
#define CP_WAIT(n)  asm volatile("cp.async.wait_group %0;" :: "n"(n) : "memory")

__device__ __forceinline__ void mma_f16(float& d0, float& d1, float& d2, float& d3,
                                        uint32_t a0, uint32_t a1, uint32_t a2, uint32_t a3,
                                        uint32_t b0, uint32_t b1) {
    asm volatile(
        "mma.sync.aligned.m16n8k16.row.col.f32.f16.f16.f32 "
        "{%0,%1,%2,%3}, {%4,%5,%6,%7}, {%8,%9}, {%0,%1,%2,%3};"
        : "+f"(d0), "+f"(d1), "+f"(d2), "+f"(d3)
        : "r"(a0), "r"(a1), "r"(a2), "r"(a3), "r"(b0), "r"(b1));
}
__device__ __forceinline__ void ldsm_x4(uint32_t& r0, uint32_t& r1,
                                        uint32_t& r2, uint32_t& r3, uint32_t addr) {
    asm volatile("ldmatrix.sync.aligned.m8n8.x4.shared.b16 {%0,%1,%2,%3}, [%4];"
                 : "=r"(r0), "=r"(r1), "=r"(r2), "=r"(r3) : "r"(addr));
}
__device__ __forceinline__ void ldsm_x4_t(uint32_t& r0, uint32_t& r1,
                                          uint32_t& r2, uint32_t& r3, uint32_t addr) {
    asm volatile("ldmatrix.sync.aligned.m8n8.x4.trans.shared.b16 {%0,%1,%2,%3}, [%4];"
                 : "=r"(r0), "=r"(r1), "=r"(r2), "=r"(r3) : "r"(addr));
}

// ======================= fp16 mma.sync GEMM =================================
// C[M, N_total] = A[M, K] (half, row-major) @ B^T (B [N_total, K] half K-major).
// CTA tile 128(M) x 256(N) x 32(K halves); 8 warps 2x4, warp tile 64x64.
// 4-stage cp.async pipeline, one __syncthreads per k-chunk, ldmatrix fragments.
#define SROWH 40                          // smem row stride in halves (80B)
#define GSTG  4
#define GST_A (128 * SROWH)               // halves per A stage
#define GST_B (256 * SROWH)               // halves per B stage
#define GEMM_SMEM ((GSTG * GST_A + GSTG * GST_B) * 2)   // 122880 bytes

template<int OUT_HALF>
__global__ void __launch_bounds__(256) gemm_mma_h(const __half* __restrict__ A,
                                                  const __half* __restrict__ B,
                                                  void* __restrict__ Cv,
                                                  int N_total, int K)
{
    extern __shared__ __half gsmh[];
    __half* Asm = gsmh;
    __half* Bsm = gsmh + GSTG * GST_A;

    const int tid  = threadIdx.x;
    const int lane = tid & 31;
    const int wid  = tid >> 5;
    const int warpM = wid >> 2;           // 0..1 -> 64 rows
    const int warpN = wid & 3;            // 0..3 -> 64 cols
    const int r0 = lane >> 2;
    const int c0 = lane & 3;
    const int lr = lane & 7;
    const int lg = lane >> 3;

    const int bm0 = blockIdx.y * 128;
    const int bn0 = blockIdx.x * 256;

    float acc[4][8][4];
#pragma unroll
    for (int mt = 0; mt < 4; mt++)
#pragma unroll
        for (int nt = 0; nt < 8; nt++)
#pragma unroll
            for (int r = 0; r < 4; r++) acc[mt][nt][r] = 0.f;

    const int nkt = K / 32;

    auto load_tiles = [&](int stg, int k0) {
#pragma unroll
        for (int i = 0; i < 2; i++) {     // A: 512 chunks
            int ch  = tid + i * 256;
            int row = ch >> 2;
            int off = (ch & 3) * 8;
            cp_async16(smem_u32(&Asm[stg * GST_A + row * SROWH + off]),
                       &A[(size_t)(bm0 + row) * K + k0 + off]);
        }
#pragma unroll
        for (int i = 0; i < 4; i++) {     // B: 1024 chunks
            int ch  = tid + i * 256;
            int row = ch >> 2;
            int off = (ch & 3) * 8;
            cp_async16(smem_u32(&Bsm[stg * GST_B + row * SROWH + off]),
                       &B[(size_t)(bn0 + row) * K + k0 + off]);
        }
    };

#pragma unroll
    for (int s = 0; s < 3; s++) { load_tiles(s, s * 32); CP_COMMIT(); }

    for (int t = 0; t < nkt; t++) {
        CP_WAIT(2);
        __syncthreads();

        const __half* Ab = &Asm[(t & 3) * GST_A];
        const __half* Bb = &Bsm[(t & 3) * GST_B];
#pragma unroll
        for (int k16 = 0; k16 < 2; k16++) {
            const int kk0 = k16 * 16;
            uint32_t af[4][4];
#pragma unroll
            for (int mt = 0; mt < 4; mt++)
                ldsm_x4(af[mt][0], af[mt][1], af[mt][2], af[mt][3],
                        smem_u32(&Ab[(warpM * 64 + mt * 16 + (lg & 1) * 8 + lr) * SROWH
                                     + kk0 + (lg >> 1) * 8]));
            uint32_t bf[4][4];
#pragma unroll
            for (int np = 0; np < 4; np++)
                ldsm_x4(bf[np][0], bf[np][1], bf[np][2], bf[np][3],
                        smem_u32(&Bb[(warpN * 64 + np * 16 + (lg >> 1) * 8 + lr) * SROWH
                                     + kk0 + (lg & 1) * 8]));
#pragma unroll
            for (int mt = 0; mt < 4; mt++)
#pragma unroll
                for (int nt = 0; nt < 8; nt++)
                    mma_f16(acc[mt][nt][0], acc[mt][nt][1],
                            acc[mt][nt][2], acc[mt][nt][3],
                            af[mt][0], af[mt][1], af[mt][2], af[mt][3],
                            bf[nt >> 1][(nt & 1) * 2], bf[nt >> 1][(nt & 1) * 2 + 1]);
        }

        if (t + 3 < nkt) load_tiles((t + 3) & 3, (t + 3) * 32);
        CP_COMMIT();
    }

#pragma unroll
    for (int mt = 0; mt < 4; mt++) {
        int row = bm0 + warpM * 64 + mt * 16 + r0;
#pragma unroll
        for (int nt = 0; nt < 8; nt++) {
            int col = bn0 + warpN * 64 + nt * 8 + c0 * 2;
            if (OUT_HALF) {
                __half* C = (__half*)Cv;
                *(half2*)&C[(size_t)row * N_total + col] =
                    __floats2half2_rn(acc[mt][nt][0], acc[mt][nt][1]);
                *(half2*)&C[(size_t)(row + 8) * N_total + col] =
                    __floats2half2_rn(acc[mt][nt][2], acc[mt][nt][3]);
            } else {
                float* C = (float*)Cv;
                *(float2*)&C[(size_t)row * N_total + col] =
                    make_float2(acc[mt][nt][0], acc[mt][nt][1]);
                *(float2*)&C[(size_t)(row + 8) * N_total + col] =
                    make_float2(acc[mt][nt][2], acc[mt][nt][3]);
            }
        }
    }
}

// ======================= prep kernels =======================================
__global__ void __launch_bounds__(256) conv_h_kernel(const float4* __restrict__ in,
                                                     __half* __restrict__ out, int n4)
{
    int i = blockIdx.x * blockDim.x + threadIdx.x;
    if (i < n4) {
        float4 v = in[i];
        half2 h0 = __floats2half2_rn(v.x, v.y);
        half2 h1 = __floats2half2_rn(v.z, v.w);
        *(uint2*)&out[i * 4] = make_uint2(*(uint32_t*)&h0, *(uint32_t*)&h1);
    }
}

// out[n, k] = half(in[k, n]); in is [K, N] row-major float
__global__ void __launch_bounds__(256) transpose_h_kernel(const float* __restrict__ in,
                                                          __half* __restrict__ out,
                                                          int K, int N)
{
    __shared__ float t[32][33];
    int n0 = blockIdx.x * 32, k0 = blockIdx.y * 32;
    int x = threadIdx.x, y = threadIdx.y;
#pragma unroll
    for (int j = 0; j < 32; j += 8)
        t[y + j][x] = in[(size_t)(k0 + y + j) * N + n0 + x];
    __syncthreads();
#pragma unroll
    for (int j = 0; j < 32; j += 8)
        out[(size_t)(n0 + y + j) * K + k0 + x] = __float2half(t[x][y + j]);
}

// ---------------- RoPE (in place on fused qkv buffer) -----------------------
__global__ void __launch_bounds__(256) rope_kernel(const float* __restrict__ cosb,
                                                   const float* __restrict__ sinb)
{
    int idx = blockIdx.x * blockDim.x + threadIdx.x;
    int p    = idx & 63;
    int rest = idx >> 6;
    int head = rest % (NH + NG);
    int bs   = rest / (NH + NG);
    int s    = bs & (SS - 1);

    float c  = cosb[s * HD + p];
    float sn = sinb[s * HD + p];

    int colbase = (head < NH) ? head * HD : NH * HD + (head - NH) * HD;
    size_t base = (size_t)bs * NQKV + colbase;

    float x0 = __half2float(g_qkvh[base + p]);
    float x1 = __half2float(g_qkvh[base + p + 64]);
    g_qkvh[base + p]      = __float2half(x0 * c - x1 * sn);
    g_qkvh[base + p + 64] = __float2half(x1 * c + x0 * sn);
}

// ======================= flash attention (fp16 mma) =========================
// CTA: 128 q rows, 64-token K tiles, 256 threads = 8 warps (m16 slab each).
#define AQPH 136
#define SSPH 72
#define AH_QS 0
#define AH_KS (AH_QS + 128 * AQPH)
#define AH_VS (AH_KS + 64 * AQPH)
#define AH_SS (AH_VS + 64 * AQPH)
#define ATTN_SMEM ((AH_SS + 128 * SSPH) * 2)

__global__ void __launch_bounds__(256) attn_mma_kernel()
{
    extern __shared__ __half smh[];
    __half* Qs = smh + AH_QS;
    __half* Ks = smh + AH_KS;
    __half* Vs = smh + AH_VS;
    __half* Ss = smh + AH_SS;

    const int tid  = threadIdx.x;
    const int lane = tid & 31;
    const int wid  = tid >> 5;
    const int r0   = lane >> 2;
    const int c0   = lane & 3;
    const int lr   = lane & 7;
    const int lg   = lane >> 3;
    const int slab = wid * 16;

    const int qt = gridDim.x - 1 - blockIdx.x;
    const int h  = blockIdx.y;
    const int b  = blockIdx.z;
    const int g  = h >> 2;
    const float scale = 0.08838834764831845f;
    const int qrow0 = qt * 128;
    const int grow0 = b * SS + qrow0;

    const int qcol = h * HD;
    const int kcol = NH * HD + g * HD;
    const int vcol = NH * HD + NG * HD + g * HD;

#pragma unroll
    for (int i = 0; i < 8; i++) {
        int ch = i * 256 + tid;
        int r = ch >> 4, c8 = (ch & 15) * 8;
        *(uint4*)&Qs[r * AQPH + c8] =
            *(const uint4*)&g_qkvh[(size_t)(grow0 + r) * NQKV + qcol + c8];
    }

    float m_a = -INFINITY, m_b = -INFINITY;
    float l_a = 0.f,       l_b = 0.f;

    float o[16][4];
#pragma unroll
    for (int nt = 0; nt < 16; nt++)
#pragma unroll
        for (int r = 0; r < 4; r++) o[nt][r] = 0.f;

    const int nkt = 2 * qt + 2;

    for (int kt = 0; kt < nkt; kt++) {
        __syncthreads();
        const int krow0 = b * SS + kt * 64;
#pragma unroll
        for (int i = 0; i < 4; i++) {
            int ch = i * 256 + tid;
            int r = ch >> 4, c8 = (ch & 15) * 8;
            size_t rowoff = (size_t)(krow0 + r) * NQKV;
            *(uint4*)&Ks[r * AQPH + c8] = *(const uint4*)&g_qkvh[rowoff + kcol + c8];
            *(uint4*)&Vs[r * AQPH + c8] = *(const uint4*)&g_qkvh[rowoff + vcol + c8];
        }
        __syncthreads();

        float sacc[8][4];
#pragma unroll
        for (int nt = 0; nt < 8; nt++)
#pragma unroll
            for (int r = 0; r < 4; r++) sacc[nt][r] = 0.f;

#pragma unroll
        for (int k16 = 0; k16 < 8; k16++) {
            const int kk0 = k16 * 16;
            uint32_t a0, a1, a2, a3;
            ldsm_x4(a0, a1, a2, a3,
                    smem_u32(&Qs[(slab + (lg & 1) * 8 + lr) * AQPH + kk0 + (lg >> 1) * 8]));
            uint32_t bf[4][4];
#pragma unroll
            for (int np = 0; np < 4; np++)
                ldsm_x4(bf[np][0], bf[np][1], bf[np][2], bf[np][3],
                        smem_u32(&Ks[(np * 16 + (lg >> 1) * 8 + lr) * AQPH + kk0 + (lg & 1) * 8]));
#pragma unroll
            for (int nt = 0; nt < 8; nt++)
                mma_f16(sacc[nt][0], sacc[nt][1], sacc[nt][2], sacc[nt][3],
                        a0, a1, a2, a3,
                        bf[nt >> 1][(nt & 1) * 2], bf[nt >> 1][(nt & 1) * 2 + 1]);
        }

        const int rg_a = qrow0 + slab + r0;
        const int rg_b = rg_a + 8;
#pragma unroll
        for (int nt = 0; nt < 8; nt++) {
            int cg = kt * 64 + nt * 8 + 2 * c0;
            sacc[nt][0] = (cg     > rg_a) ? -1e30f : sacc[nt][0] * scale;
            sacc[nt][1] = (cg + 1 > rg_a) ? -1e30f : sacc[nt][1] * scale;
            sacc[nt][2] = (cg     > rg_b) ? -1e30f : sacc[nt][2] * scale;
            sacc[nt][3] = (cg + 1 > rg_b) ? -1e30f : sacc[nt][3] * scale;
        }

        float mx_a = -INFINITY, mx_b = -INFINITY;
#pragma unroll
        for (int nt = 0; nt < 8; nt++) {
            mx_a = fmaxf(mx_a, fmaxf(sacc[nt][0], sacc[nt][1]));
            mx_b = fmaxf(mx_b, fmaxf(sacc[nt][2], sacc[nt][3]));
        }
        mx_a = fmaxf(mx_a, __shfl_xor_sync(0xffffffffu, mx_a, 1));
        mx_a = fmaxf(mx_a, __shfl_xor_sync(0xffffffffu, mx_a, 2));
        mx_b = fmaxf(mx_b, __shfl_xor_sync(0xffffffffu, mx_b, 1));
        mx_b = fmaxf(mx_b, __shfl_xor_sync(0xffffffffu, mx_b, 2));

        float mnew_a = fmaxf(m_a, mx_a);
        float mnew_b = fmaxf(m_b, mx_b);
        float alpha_a = __expf(m_a - mnew_a);
        float alpha_b = __expf(m_b - mnew_b);
        m_a = mnew_a; m_b = mnew_b;

        float ps_a = 0.f, ps_b = 0.f;
#pragma unroll
        for (int nt = 0; nt < 8; nt++) {
            float e0 = __expf(sacc[nt][0] - m_a);
            float e1 = __expf(sacc[nt][1] - m_a);
            float e2 = __expf(sacc[nt][2] - m_b);
            float e3 = __expf(sacc[nt][3] - m_b);
            ps_a += e0 + e1;
            ps_b += e2 + e3;
            *(half2*)&Ss[(slab + r0) * SSPH + nt * 8 + 2 * c0]     = __floats2half2_rn(e0, e1);
            *(half2*)&Ss[(slab + r0 + 8) * SSPH + nt * 8 + 2 * c0] = __floats2half2_rn(e2, e3);
        }
        ps_a += __shfl_xor_sync(0xffffffffu, ps_a, 1);
        ps_a += __shfl_xor_sync(0xffffffffu, ps_a, 2);
        ps_b += __shfl_xor_sync(0xffffffffu, ps_b, 1);
        ps_b += __shfl_xor_sync(0xffffffffu, ps_b, 2);
        l_a = l_a * alpha_a + ps_a;
        l_b = l_b * alpha_b + ps_b;

#pragma unroll
        for (int nt = 0; nt < 16; nt++) {
            o[nt][0] *= alpha_a; o[nt][1] *= alpha_a;
            o[nt][2] *= alpha_b; o[nt][3] *= alpha_b;
        }

        __syncwarp();

#pragma unroll
        for (int k16 = 0; k16 < 4; k16++) {
            const int kk = k16 * 16;
            uint32_t a0, a1, a2, a3;
            ldsm_x4(a0, a1, a2, a3,
                    smem_u32(&Ss[(slab + (lg & 1) * 8 + lr) * SSPH + kk + (lg >> 1) * 8]));
            uint32_t bf[8][4];
#pragma unroll
            for (int np = 0; np < 8; np++)
                ldsm_x4_t(bf[np][0], bf[np][1], bf[np][2], bf[np][3],
                          smem_u32(&Vs[(kk + (lg & 1) * 8 + lr) * AQPH + np * 16 + (lg >> 1) * 8]));
#pragma unroll
            for (int nt = 0; nt < 16; nt++)
                mma_f16(o[nt][0], o[nt][1], o[nt][2], o[nt][3],
                        a0, a1, a2, a3,
                        bf[nt >> 1][(nt & 1) * 2], bf[nt >> 1][(nt & 1) * 2 + 1]);
        }
    }

    float la = 1.f / l_a;
    float lb = 1.f / l_b;
    const size_t rowa = (size_t)(grow0 + slab + r0) * (NH * HD) + h * HD;
    const size_t rowb = (size_t)(grow0 + slab + r0 + 8) * (NH * HD) + h * HD;
#pragma unroll
    for (int nt = 0; nt < 16; nt++) {
        int c = nt * 8 + 2 * c0;
        *(half2*)&g_attnh[rowa + c] = __floats2half2_rn(o[nt][0] * la, o[nt][1] * la);
        *(half2*)&g_attnh[rowb + c] = __floats2half2_rn(o[nt][2] * lb, o[nt][3] * lb);
    }
}

// ======================= host side ==========================================
extern "C" void kernel_launch(void* const* d_in, const int* in_sizes, int n_in,
                              void* d_out, int out_size)
{
    const float* x    = (const float*)d_in[0];
    const float* cosb = (const float*)d_in[1];
    const float* sinb = (const float*)d_in[2];
    const float* Wq   = (const float*)d_in[3];
    const float* Wk   = (const float*)d_in[4];
    const float* Wv   = (const float*)d_in[5];
    const float* Wo   = (const float*)d_in[6];
    float* out = (float*)d_out;

    __half *xh, *wqkvt, *woth, *qkvh, *ah;
    cudaGetSymbolAddress((void**)&xh,    g_xh);
    cudaGetSymbolAddress((void**)&wqkvt, g_wqkvt);
    cudaGetSymbolAddress((void**)&woth,  g_woth);
    cudaGetSymbolAddress((void**)&qkvh,  g_qkvh);
    cudaGetSymbolAddress((void**)&ah,    g_attnh);

    const int M = BB * SS;       // 4096

    cudaFuncSetAttribute(gemm_mma_h<0>, cudaFuncAttributeMaxDynamicSharedMemorySize, GEMM_SMEM);
    cudaFuncSetAttribute(gemm_mma_h<1>, cudaFuncAttributeMaxDynamicSharedMemorySize, GEMM_SMEM);
    cudaFuncSetAttribute(attn_mma_kernel, cudaFuncAttributeMaxDynamicSharedMemorySize,
                         ATTN_SMEM);

    // 1) half(x); fused weight transpose into g_wqkvt rows [Q | K | V]; Wo^T
    int n4 = M * HIDN / 4;
    conv_h_kernel<<<(n4 + 255) / 256, 256>>>((const float4*)x, xh, n4);
    transpose_h_kernel<<<dim3((NH * HD) / 32, HIDN / 32), dim3(32, 8)>>>(
        Wq, wqkvt, HIDN, NH * HD);
    transpose_h_kernel<<<dim3((NG * HD) / 32, HIDN / 32), dim3(32, 8)>>>(
        Wk, wqkvt + (size_t)NH * HD * HIDN, HIDN, NG * HD);
    transpose_h_kernel<<<dim3((NG * HD) / 32, HIDN / 32), dim3(32, 8)>>>(
        Wv, wqkvt + (size_t)(NH + NG) * HD * HIDN, HIDN, NG * HD);
    transpose_h_kernel<<<dim3(HIDN / 32, (NH * HD) / 32), dim3(32, 8)>>>(
        Wo, woth, NH * HD, HIDN);

    // 2) fused QKV projection (fp16 mma, half output)
    gemm_mma_h<1><<<dim3(NQKV / 256, M / 128), 256, GEMM_SMEM>>>(xh, wqkvt, qkvh, NQKV, HIDN);

    // 3) RoPE (in place on fused buffer)
    int nrope = BB * SS * (NH + NG) * 64;
    rope_kernel<<<nrope / 256, 256>>>(cosb, sinb);

    // 4) attention (fp16 mma flash)
    attn_mma_kernel<<<dim3(SS / 128, NH, BB), 256, ATTN_SMEM>>>();

    // 5) output projection (fp32 output)
    gemm_mma_h<0><<<dim3(HIDN / 256, M / 128), 256, GEMM_SMEM>>>(ah, woth, out, HIDN, NH * HD);
}

// round 11
// speedup vs baseline: 7.4165x; 1.0268x over previous
#include <cuda_runtime.h>
#include <cuda_fp16.h>
#include <math.h>
#include <stdint.h>

#define BB  2
#define SS  2048
#define HIDN 2048
#define NH  16
#define NG  4
#define HD  128
#define NQKV (NH * HD + 2 * NG * HD)     // 3072 fused output cols

// ---------------- scratch (static device globals; no allocs) ----------------
__device__ __half g_xh   [(size_t)BB*SS*HIDN];     // half(x)
__device__ __half g_wqkvt[(size_t)NQKV*HIDN];      // [Wq;Wk;Wv]^T [3072, 2048]
__device__ __half g_woth [(size_t)NH*HD*HIDN];     // Wo^T half
__device__ __half g_qkvh [(size_t)BB*SS*NQKV];     // fused qkv, rope in-place
__device__ __half g_attnh[(size_t)BB*SS*NH*HD];    // attn out (half)

// ======================= helpers ============================================
__device__ __forceinline__ uint32_t smem_u32(const void* p) {
    uint32_t a;
    asm("{ .reg .u64 t; cvta.to.shared.u64 t, %1; cvt.u32.u64 %0, t; }"
        : "=r"(a) : "l"(p));
    return a;
}
__device__ __forceinline__ void cp_async16(uint32_t daddr, const void* gptr) {
    asm volatile("cp.async.cg.shared.global [%0], [%1], 16;"
                 :: "r"(daddr), "l"(gptr) : "memory");
}
#define CP_COMMIT() asm volatile("cp.async.commit_group;" ::: "memory")
#define CP_WAIT(n)  asm volatile("cp.async.wait_group %0;" :: "n"(n) : "memory")

__device__ __forceinline__ void mma_f16(float& d0, float& d1, float& d2, float& d3,
                                        uint32_t a0, uint32_t a1, uint32_t a2, uint32_t a3,
                                        uint32_t b0, uint32_t b1) {
    asm volatile(
        "mma.sync.aligned.m16n8k16.row.col.f32.f16.f16.f32 "
        "{%0,%1,%2,%3}, {%4,%5,%6,%7}, {%8,%9}, {%0,%1,%2,%3};"
        : "+f"(d0), "+f"(d1), "+f"(d2), "+f"(d3)
        : "r"(a0), "r"(a1), "r"(a2), "r"(a3), "r"(b0), "r"(b1));
}
__device__ __forceinline__ void ldsm_x4(uint32_t& r0, uint32_t& r1,
                                        uint32_t& r2, uint32_t& r3, uint32_t addr) {
    asm volatile("ldmatrix.sync.aligned.m8n8.x4.shared.b16 {%0,%1,%2,%3}, [%4];"
                 : "=r"(r0), "=r"(r1), "=r"(r2), "=r"(r3) : "r"(addr));
}
__device__ __forceinline__ void ldsm_x4_t(uint32_t& r0, uint32_t& r1,
                                          uint32_t& r2, uint32_t& r3, uint32_t addr) {
    asm volatile("ldmatrix.sync.aligned.m8n8.x4.trans.shared.b16 {%0,%1,%2,%3}, [%4];"
                 : "=r"(r0), "=r"(r1), "=r"(r2), "=r"(r3) : "r"(addr));
}

// ======================= fp16 mma.sync GEMM (R9, unchanged) =================
#define SROWH 40
#define GSTG  4
#define GST_A (128 * SROWH)
#define GST_B (256 * SROWH)
#define GEMM_SMEM ((GSTG * GST_A + GSTG * GST_B) * 2)

template<int OUT_HALF>
__global__ void __launch_bounds__(256) gemm_mma_h(const __half* __restrict__ A,
                                                  const __half* __restrict__ B,
                                                  void* __restrict__ Cv,
                                                  int N_total, int K)
{
    extern __shared__ __half gsmh[];
    __half* Asm = gsmh;
    __half* Bsm = gsmh + GSTG * GST_A;

    const int tid  = threadIdx.x;
    const int lane = tid & 31;
    const int wid  = tid >> 5;
    const int warpM = wid >> 2;
    const int warpN = wid & 3;
    const int r0 = lane >> 2;
    const int c0 = lane & 3;
    const int lr = lane & 7;
    const int lg = lane >> 3;

    const int bm0 = blockIdx.y * 128;
    const int bn0 = blockIdx.x * 256;

    float acc[4][8][4];
#pragma unroll
    for (int mt = 0; mt < 4; mt++)
#pragma unroll
        for (int nt = 0; nt < 8; nt++)
#pragma unroll
            for (int r = 0; r < 4; r++) acc[mt][nt][r] = 0.f;

    const int nkt = K / 32;

    auto load_tiles = [&](int stg, int k0) {
#pragma unroll
        for (int i = 0; i < 2; i++) {
            int ch  = tid + i * 256;
            int row = ch >> 2;
            int off = (ch & 3) * 8;
            cp_async16(smem_u32(&Asm[stg * GST_A + row * SROWH + off]),
                       &A[(size_t)(bm0 + row) * K + k0 + off]);
        }
#pragma unroll
        for (int i = 0; i < 4; i++) {
            int ch  = tid + i * 256;
            int row = ch >> 2;
            int off = (ch & 3) * 8;
            cp_async16(smem_u32(&Bsm[stg * GST_B + row * SROWH + off]),
                       &B[(size_t)(bn0 + row) * K + k0 + off]);
        }
    };

#pragma unroll
    for (int s = 0; s < 3; s++) { load_tiles(s, s * 32); CP_COMMIT(); }

    for (int t = 0; t < nkt; t++) {
        CP_WAIT(2);
        __syncthreads();

        const __half* Ab = &Asm[(t & 3) * GST_A];
        const __half* Bb = &Bsm[(t & 3) * GST_B];
#pragma unroll
        for (int k16 = 0; k16 < 2; k16++) {
            const int kk0 = k16 * 16;
            uint32_t af[4][4];
#pragma unroll
            for (int mt = 0; mt < 4; mt++)
                ldsm_x4(af[mt][0], af[mt][1], af[mt][2], af[mt][3],
                        smem_u32(&Ab[(warpM * 64 + mt * 16 + (lg & 1) * 8 + lr) * SROWH
                                     + kk0 + (lg >> 1) * 8]));
            uint32_t bf[4][4];
#pragma unroll
            for (int np = 0; np < 4; np++)
                ldsm_x4(bf[np][0], bf[np][1], bf[np][2], bf[np][3],
                        smem_u32(&Bb[(warpN * 64 + np * 16 + (lg >> 1) * 8 + lr) * SROWH
                                     + kk0 + (lg & 1) * 8]));
#pragma unroll
            for (int mt = 0; mt < 4; mt++)
#pragma unroll
                for (int nt = 0; nt < 8; nt++)
                    mma_f16(acc[mt][nt][0], acc[mt][nt][1],
                            acc[mt][nt][2], acc[mt][nt][3],
                            af[mt][0], af[mt][1], af[mt][2], af[mt][3],
                            bf[nt >> 1][(nt & 1) * 2], bf[nt >> 1][(nt & 1) * 2 + 1]);
        }

        if (t + 3 < nkt) load_tiles((t + 3) & 3, (t + 3) * 32);
        CP_COMMIT();
    }

#pragma unroll
    for (int mt = 0; mt < 4; mt++) {
        int row = bm0 + warpM * 64 + mt * 16 + r0;
#pragma unroll
        for (int nt = 0; nt < 8; nt++) {
            int col = bn0 + warpN * 64 + nt * 8 + c0 * 2;
            if (OUT_HALF) {
                __half* C = (__half*)Cv;
                *(half2*)&C[(size_t)row * N_total + col] =
                    __floats2half2_rn(acc[mt][nt][0], acc[mt][nt][1]);
                *(half2*)&C[(size_t)(row + 8) * N_total + col] =
                    __floats2half2_rn(acc[mt][nt][2], acc[mt][nt][3]);
            } else {
                float* C = (float*)Cv;
                *(float2*)&C[(size_t)row * N_total + col] =
                    make_float2(acc[mt][nt][0], acc[mt][nt][1]);
                *(float2*)&C[(size_t)(row + 8) * N_total + col] =
                    make_float2(acc[mt][nt][2], acc[mt][nt][3]);
            }
        }
    }
}

// ======================= prep kernels =======================================
__global__ void __launch_bounds__(256) conv_h_kernel(const float4* __restrict__ in,
                                                     __half* __restrict__ out, int n4)
{
    int i = blockIdx.x * blockDim.x + threadIdx.x;
    if (i < n4) {
        float4 v = in[i];
        half2 h0 = __floats2half2_rn(v.x, v.y);
        half2 h1 = __floats2half2_rn(v.z, v.w);
        *(uint2*)&out[i * 4] = make_uint2(*(uint32_t*)&h0, *(uint32_t*)&h1);
    }
}

__global__ void __launch_bounds__(256) transpose_h_kernel(const float* __restrict__ in,
                                                          __half* __restrict__ out,
                                                          int K, int N)
{
    __shared__ float t[32][33];
    int n0 = blockIdx.x * 32, k0 = blockIdx.y * 32;
    int x = threadIdx.x, y = threadIdx.y;
#pragma unroll
    for (int j = 0; j < 32; j += 8)
        t[y + j][x] = in[(size_t)(k0 + y + j) * N + n0 + x];
    __syncthreads();
#pragma unroll
    for (int j = 0; j < 32; j += 8)
        out[(size_t)(n0 + y + j) * K + k0 + x] = __float2half(t[x][y + j]);
}

// ---------------- RoPE (in place on fused qkv buffer) -----------------------
__global__ void __launch_bounds__(256) rope_kernel(const float* __restrict__ cosb,
                                                   const float* __restrict__ sinb)
{
    int idx = blockIdx.x * blockDim.x + threadIdx.x;
    int p    = idx & 63;
    int rest = idx >> 6;
    int head = rest % (NH + NG);
    int bs   = rest / (NH + NG);
    int s    = bs & (SS - 1);

    float c  = cosb[s * HD + p];
    float sn = sinb[s * HD + p];

    int colbase = (head < NH) ? head * HD : NH * HD + (head - NH) * HD;
    size_t base = (size_t)bs * NQKV + colbase;

    float x0 = __half2float(g_qkvh[base + p]);
    float x1 = __half2float(g_qkvh[base + p + 64]);
    g_qkvh[base + p]      = __float2half(x0 * c - x1 * sn);
    g_qkvh[base + p + 64] = __float2half(x1 * c + x0 * sn);
}

// ======================= flash attention (fp16 mma, cp.async KV) ============
// CTA: 128 q rows, 64-token K tiles, 256 threads = 8 warps (m16 slab each).
// Double-buffered cp.async K/V prefetch; one __syncthreads per kt-iter.
#define AQPH 136
#define SSPH 72
#define AH_QS 0
#define AH_KV (AH_QS + 128 * AQPH)            // 2 stages x (K 64*AQPH + V 64*AQPH)
#define KVSTG (2 * 64 * AQPH)
#define AH_SS (AH_KV + 2 * KVSTG)
#define ATTN_SMEM ((AH_SS + 128 * SSPH) * 2)  // 122880 B

__global__ void __launch_bounds__(256) attn_mma_kernel()
{
    extern __shared__ __half smh[];
    __half* Qs = smh + AH_QS;
    __half* Ss = smh + AH_SS;

    const int tid  = threadIdx.x;
    const int lane = tid & 31;
    const int wid  = tid >> 5;
    const int r0   = lane >> 2;
    const int c0   = lane & 3;
    const int lr   = lane & 7;
    const int lg   = lane >> 3;
    const int slab = wid * 16;

    const int qt = gridDim.x - 1 - blockIdx.x;
    const int h  = blockIdx.y;
    const int b  = blockIdx.z;
    const int g  = h >> 2;
    const float scale = 0.08838834764831845f;
    const int qrow0 = qt * 128;
    const int grow0 = b * SS + qrow0;

    const int qcol = h * HD;
    const int kcol = NH * HD + g * HD;
    const int vcol = NH * HD + NG * HD + g * HD;

    // ---- cp.async K/V stage loader: 4 chunks K + 4 chunks V per thread ----
    auto load_kv = [&](int stg, int kt) {
        const int krow0 = b * SS + kt * 64;
        __half* Kd = smh + AH_KV + stg * KVSTG;
        __half* Vd = Kd + 64 * AQPH;
#pragma unroll
        for (int i = 0; i < 4; i++) {
            int ch = i * 256 + tid;          // 0..1023
            int r = ch >> 4, c8 = (ch & 15) * 8;
            size_t rowoff = (size_t)(krow0 + r) * NQKV;
            cp_async16(smem_u32(&Kd[r * AQPH + c8]), &g_qkvh[rowoff + kcol + c8]);
            cp_async16(smem_u32(&Vd[r * AQPH + c8]), &g_qkvh[rowoff + vcol + c8]);
        }
    };

    // ---- load Q tile (plain loads, once) ----
#pragma unroll
    for (int i = 0; i < 8; i++) {
        int ch = i * 256 + tid;
        int r = ch >> 4, c8 = (ch & 15) * 8;
        *(uint4*)&Qs[r * AQPH + c8] =
            *(const uint4*)&g_qkvh[(size_t)(grow0 + r) * NQKV + qcol + c8];
    }

    float m_a = -INFINITY, m_b = -INFINITY;
    float l_a = 0.f,       l_b = 0.f;

    float o[16][4];
#pragma unroll
    for (int nt = 0; nt < 16; nt++)
#pragma unroll
        for (int r = 0; r < 4; r++) o[nt][r] = 0.f;

    const int nkt = 2 * qt + 2;

    // prologue: prefetch tile 0
    load_kv(0, 0);
    CP_COMMIT();

    for (int kt = 0; kt < nkt; kt++) {
        CP_WAIT(0);              // this thread's chunks of tile kt landed
        __syncthreads();         // all threads' chunks visible; prev compute done

        // prefetch kt+1 into the other stage (its last reader was iter kt-1)
        if (kt + 1 < nkt) { load_kv((kt + 1) & 1, kt + 1); CP_COMMIT(); }

        const __half* Ks = smh + AH_KV + (kt & 1) * KVSTG;
        const __half* Vs = Ks + 64 * AQPH;

        // ---- QK^T : 16 rows x 64 cols, K=128 (8 k16 steps) ----
        float sacc[8][4];
#pragma unroll
        for (int nt = 0; nt < 8; nt++)
#pragma unroll
            for (int r = 0; r < 4; r++) sacc[nt][r] = 0.f;

#pragma unroll
        for (int k16 = 0; k16 < 8; k16++) {
            const int kk0 = k16 * 16;
            uint32_t a0, a1, a2, a3;
            ldsm_x4(a0, a1, a2, a3,
                    smem_u32(&Qs[(slab + (lg & 1) * 8 + lr) * AQPH + kk0 + (lg >> 1) * 8]));
            uint32_t bf[4][4];
#pragma unroll
            for (int np = 0; np < 4; np++)
                ldsm_x4(bf[np][0], bf[np][1], bf[np][2], bf[np][3],
                        smem_u32(&Ks[(np * 16 + (lg >> 1) * 8 + lr) * AQPH + kk0 + (lg & 1) * 8]));
#pragma unroll
            for (int nt = 0; nt < 8; nt++)
                mma_f16(sacc[nt][0], sacc[nt][1], sacc[nt][2], sacc[nt][3],
                        a0, a1, a2, a3,
                        bf[nt >> 1][(nt & 1) * 2], bf[nt >> 1][(nt & 1) * 2 + 1]);
        }

        // ---- scale + causal mask ----
        const int rg_a = qrow0 + slab + r0;
        const int rg_b = rg_a + 8;
#pragma unroll
        for (int nt = 0; nt < 8; nt++) {
            int cg = kt * 64 + nt * 8 + 2 * c0;
            sacc[nt][0] = (cg     > rg_a) ? -1e30f : sacc[nt][0] * scale;
            sacc[nt][1] = (cg + 1 > rg_a) ? -1e30f : sacc[nt][1] * scale;
            sacc[nt][2] = (cg     > rg_b) ? -1e30f : sacc[nt][2] * scale;
            sacc[nt][3] = (cg + 1 > rg_b) ? -1e30f : sacc[nt][3] * scale;
        }

        // ---- row max via quad shuffle ----
        float mx_a = -INFINITY, mx_b = -INFINITY;
#pragma unroll
        for (int nt = 0; nt < 8; nt++) {
            mx_a = fmaxf(mx_a, fmaxf(sacc[nt][0], sacc[nt][1]));
            mx_b = fmaxf(mx_b, fmaxf(sacc[nt][2], sacc[nt][3]));
        }
        mx_a = fmaxf(mx_a, __shfl_xor_sync(0xffffffffu, mx_a, 1));
        mx_a = fmaxf(mx_a, __shfl_xor_sync(0xffffffffu, mx_a, 2));
        mx_b = fmaxf(mx_b, __shfl_xor_sync(0xffffffffu, mx_b, 1));
        mx_b = fmaxf(mx_b, __shfl_xor_sync(0xffffffffu, mx_b, 2));

        float mnew_a = fmaxf(m_a, mx_a);
        float mnew_b = fmaxf(m_b, mx_b);
        float alpha_a = __expf(m_a - mnew_a);
        float alpha_b = __expf(m_b - mnew_b);
        m_a = mnew_a; m_b = mnew_b;

        // ---- exp + partial sums, write P (half) to own rows ----
        float ps_a = 0.f, ps_b = 0.f;
#pragma unroll
        for (int nt = 0; nt < 8; nt++) {
            float e0 = __expf(sacc[nt][0] - m_a);
            float e1 = __expf(sacc[nt][1] - m_a);
            float e2 = __expf(sacc[nt][2] - m_b);
            float e3 = __expf(sacc[nt][3] - m_b);
            ps_a += e0 + e1;
            ps_b += e2 + e3;
            *(half2*)&Ss[(slab + r0) * SSPH + nt * 8 + 2 * c0]     = __floats2half2_rn(e0, e1);
            *(half2*)&Ss[(slab + r0 + 8) * SSPH + nt * 8 + 2 * c0] = __floats2half2_rn(e2, e3);
        }
        ps_a += __shfl_xor_sync(0xffffffffu, ps_a, 1);
        ps_a += __shfl_xor_sync(0xffffffffu, ps_a, 2);
        ps_b += __shfl_xor_sync(0xffffffffu, ps_b, 1);
        ps_b += __shfl_xor_sync(0xffffffffu, ps_b, 2);
        l_a = l_a * alpha_a + ps_a;
        l_b = l_b * alpha_b + ps_b;

#pragma unroll
        for (int nt = 0; nt < 16; nt++) {
            o[nt][0] *= alpha_a; o[nt][1] *= alpha_a;
            o[nt][2] *= alpha_b; o[nt][3] *= alpha_b;
        }

        __syncwarp();    // own-slab P stores visible to own warp's ldmatrix

        // ---- P @ V : M=16, N=128, K=64 tokens (4 k16 steps) ----
#pragma unroll
        for (int k16 = 0; k16 < 4; k16++) {
            const int kk = k16 * 16;
            uint32_t a0, a1, a2, a3;
            ldsm_x4(a0, a1, a2, a3,
                    smem_u32(&Ss[(slab + (lg & 1) * 8 + lr) * SSPH + kk + (lg >> 1) * 8]));
            uint32_t bf[8][4];
#pragma unroll
            for (int np = 0; np < 8; np++)
                ldsm_x4_t(bf[np][0], bf[np][1], bf[np][2], bf[np][3],
                          smem_u32(&Vs[(kk + (lg & 1) * 8 + lr) * AQPH + np * 16 + (lg >> 1) * 8]));
#pragma unroll
            for (int nt = 0; nt < 16; nt++)
                mma_f16(o[nt][0], o[nt][1], o[nt][2], o[nt][3],
                        a0, a1, a2, a3,
                        bf[nt >> 1][(nt & 1) * 2], bf[nt >> 1][(nt & 1) * 2 + 1]);
        }
    }

    float la = 1.f / l_a;
    float lb = 1.f / l_b;
    const size_t rowa = (size_t)(grow0 + slab + r0) * (NH * HD) + h * HD;
    const size_t rowb = (size_t)(grow0 + slab + r0 + 8) * (NH * HD) + h * HD;
#pragma unroll
    for (int nt = 0; nt < 16; nt++) {
        int c = nt * 8 + 2 * c0;
        *(half2*)&g_attnh[rowa + c] = __floats2half2_rn(o[nt][0] * la, o[nt][1] * la);
        *(half2*)&g_attnh[rowb + c] = __floats2half2_rn(o[nt][2] * lb, o[nt][3] * lb);
    }
}

// ======================= host side ==========================================
extern "C" void kernel_launch(void* const* d_in, const int* in_sizes, int n_in,
                              void* d_out, int out_size)
{
    const float* x    = (const float*)d_in[0];
    const float* cosb = (const float*)d_in[1];
    const float* sinb = (const float*)d_in[2];
    const float* Wq   = (const float*)d_in[3];
    const float* Wk   = (const float*)d_in[4];
    const float* Wv   = (const float*)d_in[5];
    const float* Wo   = (const float*)d_in[6];
    float* out = (float*)d_out;

    __half *xh, *wqkvt, *woth, *qkvh, *ah;
    cudaGetSymbolAddress((void**)&xh,    g_xh);
    cudaGetSymbolAddress((void**)&wqkvt, g_wqkvt);
    cudaGetSymbolAddress((void**)&woth,  g_woth);
    cudaGetSymbolAddress((void**)&qkvh,  g_qkvh);
    cudaGetSymbolAddress((void**)&ah,    g_attnh);

    const int M = BB * SS;       // 4096

    cudaFuncSetAttribute(gemm_mma_h<0>, cudaFuncAttributeMaxDynamicSharedMemorySize, GEMM_SMEM);
    cudaFuncSetAttribute(gemm_mma_h<1>, cudaFuncAttributeMaxDynamicSharedMemorySize, GEMM_SMEM);
    cudaFuncSetAttribute(attn_mma_kernel, cudaFuncAttributeMaxDynamicSharedMemorySize,
                         ATTN_SMEM);

    // 1) half(x); fused weight transpose into g_wqkvt rows [Q | K | V]; Wo^T
    int n4 = M * HIDN / 4;
    conv_h_kernel<<<(n4 + 255) / 256, 256>>>((const float4*)x, xh, n4);
    transpose_h_kernel<<<dim3((NH * HD) / 32, HIDN / 32), dim3(32, 8)>>>(
        Wq, wqkvt, HIDN, NH * HD);
    transpose_h_kernel<<<dim3((NG * HD) / 32, HIDN / 32), dim3(32, 8)>>>(
        Wk, wqkvt + (size_t)NH * HD * HIDN, HIDN, NG * HD);
    transpose_h_kernel<<<dim3((NG * HD) / 32, HIDN / 32), dim3(32, 8)>>>(
        Wv, wqkvt + (size_t)(NH + NG) * HD * HIDN, HIDN, NG * HD);
    transpose_h_kernel<<<dim3(HIDN / 32, (NH * HD) / 32), dim3(32, 8)>>>(
        Wo, woth, NH * HD, HIDN);

    // 2) fused QKV projection (fp16 mma, half output)
    gemm_mma_h<1><<<dim3(NQKV / 256, M / 128), 256, GEMM_SMEM>>>(xh, wqkvt, qkvh, NQKV, HIDN);

    // 3) RoPE (in place on fused buffer)
    int nrope = BB * SS * (NH + NG) * 64;
    rope_kernel<<<nrope / 256, 256>>>(cosb, sinb);

    // 4) attention (fp16 mma flash, cp.async KV pipeline)
    attn_mma_kernel<<<dim3(SS / 128, NH, BB), 256, ATTN_SMEM>>>();

    // 5) output projection (fp32 output)
    gemm_mma_h<0><<<dim3(HIDN / 256, M / 128), 256, GEMM_SMEM>>>(ah, woth, out, HIDN, NH * HD);
}